// round 1
// baseline (speedup 1.0000x reference)
#include <cuda_runtime.h>
#include <mma.h>

using namespace nvcuda;

#define NNODES 50000
#define NRELS  16
#define DIMS   128
#define NLAYER 2
#define NEDGE  600000
#define NQUERY 8192
#define PDIM   5
#define NCOL   (DIMS * (NRELS + 1))   // 2176: [self | rel0 | ... | rel15]

// -------------------- scratch (static device globals; no allocation) --------
__device__ float g_hA[NNODES * DIMS];
__device__ float g_hB[NNODES * DIMS];
__device__ float g_T[(size_t)NNODES * NCOL];          // transformed features per layer
__device__ float g_Bpack[NLAYER][DIMS * NCOL];        // packed [K, N] weights (tf32 bits)
__device__ int   g_cnt[NNODES * NRELS];
__device__ float g_w[NEDGE];

// -------------------- small kernels -----------------------------------------

__global__ void pack_weights_kernel(const float* __restrict__ Wself,
                                    const float* __restrict__ Wrel) {
    int idx = blockIdx.x * blockDim.x + threadIdx.x;
    const int total = NLAYER * DIMS * NCOL;
    if (idx >= total) return;
    int l   = idx / (DIMS * NCOL);
    int rem = idx - l * (DIMS * NCOL);
    int k   = rem / NCOL;
    int n   = rem - k * NCOL;
    float v;
    if (n < DIMS) {
        v = Wself[(l * DIMS + k) * DIMS + n];
    } else {
        int r = (n - DIMS) >> 7;
        int e = (n - DIMS) & 127;
        v = Wrel[(((size_t)(l * NRELS + r) * DIMS) + k) * DIMS + e];
    }
    g_Bpack[l][k * NCOL + n] = wmma::__float_to_tf32(v);
}

__global__ void gather_h_kernel(const int* __restrict__ node_ids,
                                const float* __restrict__ emb) {
    int t = blockIdx.x * blockDim.x + threadIdx.x;   // one float4 each
    if (t >= NNODES * (DIMS / 4)) return;
    int n = t >> 5;           // DIMS/4 == 32
    int c = t & 31;
    const float4* src = reinterpret_cast<const float4*>(emb + (size_t)node_ids[n] * DIMS);
    reinterpret_cast<float4*>(g_hA)[n * 32 + c] = src[c];
}

__global__ void zero_cnt_kernel() {
    int i = blockIdx.x * blockDim.x + threadIdx.x;
    if (i < NNODES * NRELS) g_cnt[i] = 0;
}

__global__ void count_kernel(const int* __restrict__ dst, const int* __restrict__ et) {
    int e = blockIdx.x * blockDim.x + threadIdx.x;
    if (e >= NEDGE) return;
    atomicAdd(&g_cnt[dst[e] * NRELS + et[e]], 1);
}

__global__ void weight_kernel(const int* __restrict__ dst, const int* __restrict__ et) {
    int e = blockIdx.x * blockDim.x + threadIdx.x;
    if (e >= NEDGE) return;
    int c = g_cnt[dst[e] * NRELS + et[e]];
    g_w[e] = 1.0f / (float)max(c, 1);
}

// h_next initialized with the self-transform columns of g_T
__global__ void init_self_kernel(float* __restrict__ hn) {
    int t = blockIdx.x * blockDim.x + threadIdx.x;
    if (t >= NNODES * (DIMS / 4)) return;
    int n = t >> 5;
    int c = t & 31;
    float4 v = *reinterpret_cast<const float4*>(g_T + (size_t)n * NCOL + c * 4);
    reinterpret_cast<float4*>(hn)[n * 32 + c] = v;
}

// one warp per edge: read transformed row T[src, rel-block], scale, atomic-add to h_next[dst]
__global__ void edge_agg_kernel(const int* __restrict__ src,
                                const int* __restrict__ dst,
                                const int* __restrict__ et,
                                float* __restrict__ hn) {
    int warp = (blockIdx.x * blockDim.x + threadIdx.x) >> 5;
    int lane = threadIdx.x & 31;
    if (warp >= NEDGE) return;
    int s = src[warp];
    int d = dst[warp];
    int r = et[warp];
    float we = g_w[warp];
    const float4* row = reinterpret_cast<const float4*>(
        g_T + (size_t)s * NCOL + DIMS + (size_t)r * DIMS);
    float4 v = row[lane];
    float* o = hn + (size_t)d * DIMS + lane * 4;
    atomicAdd(o + 0, v.x * we);
    atomicAdd(o + 1, v.y * we);
    atomicAdd(o + 2, v.z * we);
    atomicAdd(o + 3, v.w * we);
}

__global__ void relu_kernel(float* __restrict__ h) {
    int t = blockIdx.x * blockDim.x + threadIdx.x;
    if (t >= NNODES * (DIMS / 4)) return;
    float4 v = reinterpret_cast<float4*>(h)[t];
    v.x = fmaxf(v.x, 0.f); v.y = fmaxf(v.y, 0.f);
    v.z = fmaxf(v.z, 0.f); v.w = fmaxf(v.w, 0.f);
    reinterpret_cast<float4*>(h)[t] = v;
}

// -------------------- TF32 GEMM: C[M,NCOL] = A[M,128] @ B[128,NCOL] ----------
#define BM 128
#define BN 128
#define BK 128
#define LDS 132

__global__ void gemm_tf32_kernel(const float* __restrict__ A,
                                 const float* __restrict__ B,
                                 float* __restrict__ C, int M) {
    extern __shared__ float sm[];
    float* As = sm;               // BM x LDS
    float* Bs = sm + BM * LDS;    // BK x LDS

    const int tid = threadIdx.x;
    const int m0 = blockIdx.y * BM;
    const int n0 = blockIdx.x * BN;

    // load A tile (fp32 -> tf32)
    for (int i = tid; i < BM * BK / 4; i += 256) {
        int r = i >> 5, c4 = i & 31;
        float4 v = make_float4(0.f, 0.f, 0.f, 0.f);
        int gm = m0 + r;
        if (gm < M) v = *reinterpret_cast<const float4*>(A + (size_t)gm * DIMS + c4 * 4);
        As[r * LDS + c4 * 4 + 0] = wmma::__float_to_tf32(v.x);
        As[r * LDS + c4 * 4 + 1] = wmma::__float_to_tf32(v.y);
        As[r * LDS + c4 * 4 + 2] = wmma::__float_to_tf32(v.z);
        As[r * LDS + c4 * 4 + 3] = wmma::__float_to_tf32(v.w);
    }
    // load B tile (already tf32 bits)
    for (int i = tid; i < BK * BN / 4; i += 256) {
        int r = i >> 5, c4 = i & 31;
        float4 v = *reinterpret_cast<const float4*>(B + (size_t)r * NCOL + n0 + c4 * 4);
        *reinterpret_cast<float4*>(&Bs[r * LDS + c4 * 4]) = v;
    }
    __syncthreads();

    const int wid = tid >> 5;
    const int wm  = wid & 3;   // 4 warps over M (32 rows each)
    const int wn  = wid >> 2;  // 2 warps over N (64 cols each)

    wmma::fragment<wmma::accumulator, 16, 16, 8, float> acc[2][4];
#pragma unroll
    for (int i = 0; i < 2; i++)
#pragma unroll
        for (int j = 0; j < 4; j++) wmma::fill_fragment(acc[i][j], 0.f);

#pragma unroll
    for (int k0 = 0; k0 < BK; k0 += 8) {
        wmma::fragment<wmma::matrix_a, 16, 16, 8, wmma::precision::tf32, wmma::row_major> af[2];
        wmma::fragment<wmma::matrix_b, 16, 16, 8, wmma::precision::tf32, wmma::row_major> bf[4];
#pragma unroll
        for (int i = 0; i < 2; i++)
            wmma::load_matrix_sync(af[i], As + (wm * 32 + i * 16) * LDS + k0, LDS);
#pragma unroll
        for (int j = 0; j < 4; j++)
            wmma::load_matrix_sync(bf[j], Bs + k0 * LDS + wn * 64 + j * 16, LDS);
#pragma unroll
        for (int i = 0; i < 2; i++)
#pragma unroll
            for (int j = 0; j < 4; j++)
                wmma::mma_sync(acc[i][j], af[i], bf[j], acc[i][j]);
    }
    __syncthreads();

    // stage C in shared (reuse As region), then guarded vectorized writeout
    float* Cs = sm;
#pragma unroll
    for (int i = 0; i < 2; i++)
#pragma unroll
        for (int j = 0; j < 4; j++)
            wmma::store_matrix_sync(Cs + (wm * 32 + i * 16) * LDS + wn * 64 + j * 16,
                                    acc[i][j], LDS, wmma::mem_row_major);
    __syncthreads();

    for (int i = tid; i < BM * BN / 4; i += 256) {
        int r = i >> 5, c4 = i & 31;
        int gm = m0 + r;
        if (gm < M) {
            float4 v = *reinterpret_cast<const float4*>(&Cs[r * LDS + c4 * 4]);
            *reinterpret_cast<float4*>(C + (size_t)gm * NCOL + n0 + c4 * 4) = v;
        }
    }
}

// -------------------- scoring ------------------------------------------------
__global__ void score_kernel(const float* __restrict__ h,
                             const int* __restrict__ heads,
                             const int* __restrict__ rels,
                             const int* __restrict__ tails,
                             const float* __restrict__ rel_emb,
                             const float* __restrict__ path_feat,
                             const int* __restrict__ task_idx,
                             const float* __restrict__ delta_w,
                             const float* __restrict__ lambda_logit,
                             const float* __restrict__ rule_init,
                             float* __restrict__ out) {
    int warp = (blockIdx.x * blockDim.x + threadIdx.x) >> 5;
    int lane = threadIdx.x & 31;
    if (warp >= NQUERY) return;
    int hh = heads[warp], rr = rels[warp], tt = tails[warp];
    float4 a = reinterpret_cast<const float4*>(h + (size_t)hh * DIMS)[lane];
    float4 r = reinterpret_cast<const float4*>(rel_emb + (size_t)rr * DIMS)[lane];
    float4 b = reinterpret_cast<const float4*>(h + (size_t)tt * DIMS)[lane];
    float s = a.x * r.x * b.x + a.y * r.y * b.y + a.z * r.z * b.z + a.w * r.w * b.w;
#pragma unroll
    for (int off = 16; off > 0; off >>= 1)
        s += __shfl_xor_sync(0xFFFFFFFFu, s, off);
    if (lane == 0) {
        int idx = task_idx[0];
        float sp = 0.f;
#pragma unroll
        for (int p = 0; p < PDIM; p++)
            sp += path_feat[warp * PDIM + p] * (rule_init[idx * PDIM + p] + delta_w[idx * PDIM + p]);
        float lam = 1.0f / (1.0f + __expf(-lambda_logit[idx]));
        out[warp] = lam * s + (1.0f - lam) * sp;
    }
}

// -------------------- launcher -----------------------------------------------
extern "C" void kernel_launch(void* const* d_in, const int* in_sizes, int n_in,
                              void* d_out, int out_size) {
    const int*   node_ids   = (const int*)d_in[0];
    const int*   edge_index = (const int*)d_in[1];
    const int*   edge_type  = (const int*)d_in[2];
    const int*   heads      = (const int*)d_in[3];
    const int*   rels       = (const int*)d_in[4];
    const int*   tails      = (const int*)d_in[5];
    const float* path_feat  = (const float*)d_in[6];
    const int*   task_idx   = (const int*)d_in[7];
    const float* entity_emb = (const float*)d_in[8];
    const float* rel_emb    = (const float*)d_in[9];
    const float* W_self     = (const float*)d_in[10];
    const float* W_rel      = (const float*)d_in[11];
    const float* delta_w    = (const float*)d_in[12];
    const float* lambda_lg  = (const float*)d_in[13];
    const float* rule_init  = (const float*)d_in[14];
    float*       out        = (float*)d_out;

    const int* src = edge_index;
    const int* dst = edge_index + NEDGE;

    float *hA, *hB, *T, *Bpack;
    cudaGetSymbolAddress((void**)&hA, g_hA);
    cudaGetSymbolAddress((void**)&hB, g_hB);
    cudaGetSymbolAddress((void**)&T, g_T);
    cudaGetSymbolAddress((void**)&Bpack, g_Bpack);

    const int TPB = 256;
    const size_t gemm_smem = (size_t)(BM + BK) * LDS * sizeof(float);  // 135168
    cudaFuncSetAttribute(gemm_tf32_kernel,
                         cudaFuncAttributeMaxDynamicSharedMemorySize, (int)gemm_smem);

    // prep
    pack_weights_kernel<<<(NLAYER * DIMS * NCOL + TPB - 1) / TPB, TPB>>>(W_self, W_rel);
    gather_h_kernel<<<(NNODES * 32 + TPB - 1) / TPB, TPB>>>(node_ids, entity_emb);
    zero_cnt_kernel<<<(NNODES * NRELS + TPB - 1) / TPB, TPB>>>();
    count_kernel<<<(NEDGE + TPB - 1) / TPB, TPB>>>(dst, edge_type);
    weight_kernel<<<(NEDGE + TPB - 1) / TPB, TPB>>>(dst, edge_type);

    float* h_cur = hA;
    float* h_nxt = hB;
    for (int l = 0; l < NLAYER; l++) {
        dim3 grid(NCOL / BN, (NNODES + BM - 1) / BM);
        gemm_tf32_kernel<<<grid, 256, gemm_smem>>>(h_cur, Bpack + (size_t)l * DIMS * NCOL,
                                                   T, NNODES);
        init_self_kernel<<<(NNODES * 32 + TPB - 1) / TPB, TPB>>>(h_nxt);
        edge_agg_kernel<<<(NEDGE * 32 + TPB - 1) / TPB, TPB>>>(src, dst, edge_type, h_nxt);
        relu_kernel<<<(NNODES * 32 + TPB - 1) / TPB, TPB>>>(h_nxt);
        float* tmp = h_cur; h_cur = h_nxt; h_nxt = tmp;
    }

    score_kernel<<<(NQUERY * 32 + TPB - 1) / TPB, TPB>>>(
        h_cur, heads, rels, tails, rel_emb, path_feat, task_idx,
        delta_w, lambda_lg, rule_init, out);
}

// round 2
// speedup vs baseline: 1.1323x; 1.1323x over previous
#include <cuda_runtime.h>
#include <mma.h>

using namespace nvcuda;

#define NNODES 50000
#define MPAD   50048            // 391 * 128
#define NRELS  16
#define DIMS   128
#define NLAYER 2
#define NEDGE  600000
#define NQUERY 8192
#define PDIM   5
#define NCOL   (DIMS * (NRELS + 1))   // 2176 packed weight cols: [self | rel0..rel15]
#define TCOL   (DIMS * NRELS)         // 2048 cols materialized in T (rel blocks only)

// -------------------- scratch (static device globals; no allocation) --------
__device__ float g_hA[(size_t)MPAD * DIMS];
__device__ float g_hB[(size_t)MPAD * DIMS];
__device__ float g_T[(size_t)MPAD * TCOL];
__device__ float g_Bpack[NLAYER][DIMS * NCOL];   // [K=128, N=2176] tf32 bits
__device__ int   g_cnt[NNODES * NRELS];
__device__ float g_w[NEDGE];

// -------------------- vector RED ---------------------------------------------
__device__ __forceinline__ void red_add_v4(float* addr, float x, float y, float z, float w) {
    asm volatile("red.global.add.v4.f32 [%0], {%1, %2, %3, %4};"
                 :: "l"(addr), "f"(x), "f"(y), "f"(z), "f"(w) : "memory");
}

// -------------------- small kernels -----------------------------------------
__global__ void pack_weights_kernel(const float* __restrict__ Wself,
                                    const float* __restrict__ Wrel) {
    int idx = blockIdx.x * blockDim.x + threadIdx.x;
    const int total = NLAYER * DIMS * NCOL;
    if (idx >= total) return;
    int l   = idx / (DIMS * NCOL);
    int rem = idx - l * (DIMS * NCOL);
    int k   = rem / NCOL;
    int n   = rem - k * NCOL;
    float v;
    if (n < DIMS) {
        v = Wself[(l * DIMS + k) * DIMS + n];
    } else {
        int r = (n - DIMS) >> 7;
        int e = (n - DIMS) & 127;
        v = Wrel[(((size_t)(l * NRELS + r) * DIMS) + k) * DIMS + e];
    }
    g_Bpack[l][k * NCOL + n] = wmma::__float_to_tf32(v);
}

__global__ void gather_h_kernel(const int* __restrict__ node_ids,
                                const float* __restrict__ emb) {
    int t = blockIdx.x * blockDim.x + threadIdx.x;
    if (t >= NNODES * (DIMS / 4)) return;
    int n = t >> 5;
    int c = t & 31;
    const float4* src = reinterpret_cast<const float4*>(emb + (size_t)node_ids[n] * DIMS);
    reinterpret_cast<float4*>(g_hA)[n * 32 + c] = src[c];
}

__global__ void zero_cnt_kernel() {
    int i = blockIdx.x * blockDim.x + threadIdx.x;
    if (i < NNODES * NRELS) g_cnt[i] = 0;
}

__global__ void count_kernel(const int* __restrict__ dst, const int* __restrict__ et) {
    int e = blockIdx.x * blockDim.x + threadIdx.x;
    if (e >= NEDGE) return;
    atomicAdd(&g_cnt[dst[e] * NRELS + et[e]], 1);
}

__global__ void weight_kernel(const int* __restrict__ dst, const int* __restrict__ et) {
    int e = blockIdx.x * blockDim.x + threadIdx.x;
    if (e >= NEDGE) return;
    int c = g_cnt[dst[e] * NRELS + et[e]];
    g_w[e] = 1.0f / (float)max(c, 1);
}

// one warp per edge: read T[src, rel-block], scale, vector-RED into h_next[dst]
__global__ void edge_agg_kernel(const int* __restrict__ src,
                                const int* __restrict__ dst,
                                const int* __restrict__ et,
                                float* __restrict__ hn) {
    int warp = (blockIdx.x * blockDim.x + threadIdx.x) >> 5;
    int lane = threadIdx.x & 31;
    if (warp >= NEDGE) return;
    int s = src[warp];
    int d = dst[warp];
    int r = et[warp];
    float we = g_w[warp];
    const float4* row = reinterpret_cast<const float4*>(
        g_T + (size_t)s * TCOL + (size_t)r * DIMS);
    float4 v = row[lane];
    red_add_v4(hn + (size_t)d * DIMS + lane * 4, v.x * we, v.y * we, v.z * we, v.w * we);
}

__global__ void relu_kernel(float* __restrict__ h) {
    int t = blockIdx.x * blockDim.x + threadIdx.x;
    if (t >= NNODES * (DIMS / 4)) return;
    float4 v = reinterpret_cast<float4*>(h)[t];
    v.x = fmaxf(v.x, 0.f); v.y = fmaxf(v.y, 0.f);
    v.z = fmaxf(v.z, 0.f); v.w = fmaxf(v.w, 0.f);
    reinterpret_cast<float4*>(h)[t] = v;
}

// -------------------- TF32 GEMM: [MPAD,128] @ [128,2176] ---------------------
// Block tile 128x128. blockIdx.x == 0 -> write to h_next (self block, ld=128);
// else -> write to T at col (n0-128), ld=2048. No M guards (M padded).
#define BM 128
#define BN 128
#define BK 128
#define LDS 132

__global__ void gemm_tf32_kernel(const float* __restrict__ A,
                                 const float* __restrict__ B,
                                 float* __restrict__ T,
                                 float* __restrict__ hn) {
    extern __shared__ float sm[];
    float* As = sm;               // BM x LDS
    float* Bs = sm + BM * LDS;    // BK x LDS

    const int tid = threadIdx.x;
    const int m0 = blockIdx.y * BM;
    const int n0 = blockIdx.x * BN;

    // load A tile (fp32 -> tf32), unguarded (A padded to MPAD rows)
    for (int i = tid; i < BM * BK / 4; i += 256) {
        int r = i >> 5, c4 = i & 31;
        float4 v = *reinterpret_cast<const float4*>(A + (size_t)(m0 + r) * DIMS + c4 * 4);
        As[r * LDS + c4 * 4 + 0] = wmma::__float_to_tf32(v.x);
        As[r * LDS + c4 * 4 + 1] = wmma::__float_to_tf32(v.y);
        As[r * LDS + c4 * 4 + 2] = wmma::__float_to_tf32(v.z);
        As[r * LDS + c4 * 4 + 3] = wmma::__float_to_tf32(v.w);
    }
    // load B tile (already tf32 bits)
    for (int i = tid; i < BK * BN / 4; i += 256) {
        int r = i >> 5, c4 = i & 31;
        float4 v = *reinterpret_cast<const float4*>(B + (size_t)r * NCOL + n0 + c4 * 4);
        *reinterpret_cast<float4*>(&Bs[r * LDS + c4 * 4]) = v;
    }
    __syncthreads();

    const int wid = tid >> 5;
    const int wm  = wid & 3;   // 4 warps over M (32 rows each)
    const int wn  = wid >> 2;  // 2 warps over N (64 cols each)

    wmma::fragment<wmma::accumulator, 16, 16, 8, float> acc[2][4];
#pragma unroll
    for (int i = 0; i < 2; i++)
#pragma unroll
        for (int j = 0; j < 4; j++) wmma::fill_fragment(acc[i][j], 0.f);

#pragma unroll
    for (int k0 = 0; k0 < BK; k0 += 8) {
        wmma::fragment<wmma::matrix_a, 16, 16, 8, wmma::precision::tf32, wmma::row_major> af[2];
        wmma::fragment<wmma::matrix_b, 16, 16, 8, wmma::precision::tf32, wmma::row_major> bf[4];
#pragma unroll
        for (int i = 0; i < 2; i++)
            wmma::load_matrix_sync(af[i], As + (wm * 32 + i * 16) * LDS + k0, LDS);
#pragma unroll
        for (int j = 0; j < 4; j++)
            wmma::load_matrix_sync(bf[j], Bs + k0 * LDS + wn * 64 + j * 16, LDS);
#pragma unroll
        for (int i = 0; i < 2; i++)
#pragma unroll
            for (int j = 0; j < 4; j++)
                wmma::mma_sync(acc[i][j], af[i], bf[j], acc[i][j]);
    }

    // direct fragment writeout (no smem staging, no guards)
    float* Cout;
    size_t ldc;
    if (n0 == 0) { Cout = hn; ldc = DIMS; }
    else         { Cout = T + (n0 - DIMS); ldc = TCOL; }
#pragma unroll
    for (int i = 0; i < 2; i++)
#pragma unroll
        for (int j = 0; j < 4; j++)
            wmma::store_matrix_sync(Cout + (size_t)(m0 + wm * 32 + i * 16) * ldc
                                         + wn * 64 + j * 16,
                                    acc[i][j], ldc, wmma::mem_row_major);
}

// -------------------- scoring ------------------------------------------------
__global__ void score_kernel(const float* __restrict__ h,
                             const int* __restrict__ heads,
                             const int* __restrict__ rels,
                             const int* __restrict__ tails,
                             const float* __restrict__ rel_emb,
                             const float* __restrict__ path_feat,
                             const int* __restrict__ task_idx,
                             const float* __restrict__ delta_w,
                             const float* __restrict__ lambda_logit,
                             const float* __restrict__ rule_init,
                             float* __restrict__ out) {
    int warp = (blockIdx.x * blockDim.x + threadIdx.x) >> 5;
    int lane = threadIdx.x & 31;
    if (warp >= NQUERY) return;
    int hh = heads[warp], rr = rels[warp], tt = tails[warp];
    float4 a = reinterpret_cast<const float4*>(h + (size_t)hh * DIMS)[lane];
    float4 r = reinterpret_cast<const float4*>(rel_emb + (size_t)rr * DIMS)[lane];
    float4 b = reinterpret_cast<const float4*>(h + (size_t)tt * DIMS)[lane];
    float s = a.x * r.x * b.x + a.y * r.y * b.y + a.z * r.z * b.z + a.w * r.w * b.w;
#pragma unroll
    for (int off = 16; off > 0; off >>= 1)
        s += __shfl_xor_sync(0xFFFFFFFFu, s, off);
    if (lane == 0) {
        int idx = task_idx[0];
        float sp = 0.f;
#pragma unroll
        for (int p = 0; p < PDIM; p++)
            sp += path_feat[warp * PDIM + p] * (rule_init[idx * PDIM + p] + delta_w[idx * PDIM + p]);
        float lam = 1.0f / (1.0f + __expf(-lambda_logit[idx]));
        out[warp] = lam * s + (1.0f - lam) * sp;
    }
}

// -------------------- launcher -----------------------------------------------
extern "C" void kernel_launch(void* const* d_in, const int* in_sizes, int n_in,
                              void* d_out, int out_size) {
    const int*   node_ids   = (const int*)d_in[0];
    const int*   edge_index = (const int*)d_in[1];
    const int*   edge_type  = (const int*)d_in[2];
    const int*   heads      = (const int*)d_in[3];
    const int*   rels       = (const int*)d_in[4];
    const int*   tails      = (const int*)d_in[5];
    const float* path_feat  = (const float*)d_in[6];
    const int*   task_idx   = (const int*)d_in[7];
    const float* entity_emb = (const float*)d_in[8];
    const float* rel_emb    = (const float*)d_in[9];
    const float* W_self     = (const float*)d_in[10];
    const float* W_rel      = (const float*)d_in[11];
    const float* delta_w    = (const float*)d_in[12];
    const float* lambda_lg  = (const float*)d_in[13];
    const float* rule_init  = (const float*)d_in[14];
    float*       out        = (float*)d_out;

    const int* src = edge_index;
    const int* dst = edge_index + NEDGE;

    float *hA, *hB, *T, *Bpack;
    cudaGetSymbolAddress((void**)&hA, g_hA);
    cudaGetSymbolAddress((void**)&hB, g_hB);
    cudaGetSymbolAddress((void**)&T, g_T);
    cudaGetSymbolAddress((void**)&Bpack, g_Bpack);

    const int TPB = 256;
    const size_t gemm_smem = (size_t)(BM + BK) * LDS * sizeof(float);
    cudaFuncSetAttribute(gemm_tf32_kernel,
                         cudaFuncAttributeMaxDynamicSharedMemorySize, (int)gemm_smem);

    pack_weights_kernel<<<(NLAYER * DIMS * NCOL + TPB - 1) / TPB, TPB>>>(W_self, W_rel);
    gather_h_kernel<<<(NNODES * 32 + TPB - 1) / TPB, TPB>>>(node_ids, entity_emb);
    zero_cnt_kernel<<<(NNODES * NRELS + TPB - 1) / TPB, TPB>>>();
    count_kernel<<<(NEDGE + TPB - 1) / TPB, TPB>>>(dst, edge_type);
    weight_kernel<<<(NEDGE + TPB - 1) / TPB, TPB>>>(dst, edge_type);

    float* h_cur = hA;
    float* h_nxt = hB;
    for (int l = 0; l < NLAYER; l++) {
        dim3 grid(NCOL / BN, MPAD / BM);
        gemm_tf32_kernel<<<grid, 256, gemm_smem>>>(h_cur, Bpack + (size_t)l * DIMS * NCOL,
                                                   T, h_nxt);
        edge_agg_kernel<<<(NEDGE * 32 + TPB - 1) / TPB, TPB>>>(src, dst, edge_type, h_nxt);
        relu_kernel<<<(NNODES * 32 + TPB - 1) / TPB, TPB>>>(h_nxt);
        float* tmp = h_cur; h_cur = h_nxt; h_nxt = tmp;
    }

    score_kernel<<<(NQUERY * 32 + TPB - 1) / TPB, TPB>>>(
        h_cur, heads, rels, tails, rel_emb, path_feat, task_idx,
        delta_w, lambda_lg, rule_init, out);
}

// round 4
// speedup vs baseline: 1.6862x; 1.4892x over previous
#include <cuda_runtime.h>
#include <mma.h>
#include <cstdint>

using namespace nvcuda;

#define NNODES 50000
#define MPAD   50048            // 391 * 128
#define NRELS  16
#define DIMS   128
#define NLAYER 2
#define NEDGE  600000
#define NQUERY 8192
#define PDIM   5
#define NCOL   (DIMS * (NRELS + 1))   // 2176 packed weight cols: [self | rel0..rel15]
#define TCOL   (DIMS * NRELS)         // 2048 cols materialized in T
#define NTILES (NCOL / 128)           // 17

// -------------------- scratch (static device globals) -----------------------
__device__ float g_hA[(size_t)MPAD * DIMS];
__device__ float g_hB[(size_t)MPAD * DIMS];
__device__ float g_T[(size_t)MPAD * TCOL];
__device__ float g_Bpack[NLAYER][DIMS * NCOL];   // [K=128][N=2176] tf32 bits
__device__ int   g_cnt[NNODES * NRELS];

// -------------------- helpers -------------------------------------------------
__device__ __forceinline__ uint32_t smem_u32(const void* p) {
    uint32_t a;
    asm("{ .reg .u64 t; cvta.to.shared.u64 t, %1; cvt.u32.u64 %0, t; }" : "=r"(a) : "l"(p));
    return a;
}
__device__ __forceinline__ void red_add_v4(float* addr, float x, float y, float z, float w) {
    asm volatile("red.global.add.v4.f32 [%0], {%1, %2, %3, %4};"
                 :: "l"(addr), "f"(x), "f"(y), "f"(z), "f"(w) : "memory");
}
__device__ __forceinline__ void cp_async16(uint32_t saddr, const void* g) {
    asm volatile("cp.async.ca.shared.global [%0], [%1], 16;" :: "r"(saddr), "l"(g));
}
#define CP_COMMIT() asm volatile("cp.async.commit_group;")
#define CP_WAIT0()  asm volatile("cp.async.wait_group 0;")
#define CP_WAIT1()  asm volatile("cp.async.wait_group 1;")

// -------------------- small kernels -----------------------------------------
__global__ void pack_weights_kernel(const float* __restrict__ Wself,
                                    const float* __restrict__ Wrel) {
    int idx = blockIdx.x * blockDim.x + threadIdx.x;
    const int total = NLAYER * DIMS * NCOL;
    if (idx >= total) return;
    int l   = idx / (DIMS * NCOL);
    int rem = idx - l * (DIMS * NCOL);
    int k   = rem / NCOL;
    int n   = rem - k * NCOL;
    float v;
    if (n < DIMS) {
        v = Wself[(l * DIMS + k) * DIMS + n];
    } else {
        int r = (n - DIMS) >> 7;
        int e = (n - DIMS) & 127;
        v = Wrel[(((size_t)(l * NRELS + r) * DIMS) + k) * DIMS + e];
    }
    g_Bpack[l][k * NCOL + n] = wmma::__float_to_tf32(v);
}

__global__ void gather_h_kernel(const int* __restrict__ node_ids,
                                const float* __restrict__ emb) {
    int t = blockIdx.x * blockDim.x + threadIdx.x;
    if (t >= NNODES * (DIMS / 4)) return;
    int n = t >> 5;
    int c = t & 31;
    const float4* src = reinterpret_cast<const float4*>(emb + (size_t)node_ids[n] * DIMS);
    reinterpret_cast<float4*>(g_hA)[n * 32 + c] = src[c];
}

__global__ void zero_cnt_kernel() {
    int i = blockIdx.x * blockDim.x + threadIdx.x;
    if (i < NNODES * NRELS) g_cnt[i] = 0;
}

__global__ void count_kernel(const int* __restrict__ dst, const int* __restrict__ et) {
    int e = blockIdx.x * blockDim.x + threadIdx.x;
    if (e >= NEDGE) return;
    atomicAdd(&g_cnt[dst[e] * NRELS + et[e]], 1);
}

// one warp per edge: read T[src, rel-block], scale by 1/cnt, vector-RED into h_next[dst]
__global__ void edge_agg_kernel(const int* __restrict__ src,
                                const int* __restrict__ dst,
                                const int* __restrict__ et,
                                float* __restrict__ hn) {
    int warp = (blockIdx.x * blockDim.x + threadIdx.x) >> 5;
    int lane = threadIdx.x & 31;
    if (warp >= NEDGE) return;
    int s = src[warp];
    int d = dst[warp];
    int r = et[warp];
    int c = g_cnt[d * NRELS + r];        // >= 1 (this edge is counted)
    float we = 1.0f / (float)c;
    const float4* row = reinterpret_cast<const float4*>(
        g_T + (size_t)s * TCOL + (size_t)r * DIMS);
    float4 v = row[lane];
    red_add_v4(hn + (size_t)d * DIMS + lane * 4, v.x * we, v.y * we, v.z * we, v.w * we);
}

// -------------------- TF32 GEMM, persistent over N-tiles --------------------
// Block: 256 thr. Owns one 128-row M tile, loops over a range of 128-col N tiles.
// A converted to smem once; B double-buffered with cp.async.
#define LDSW 132
#define A_ELEMS (128 * LDSW)
#define GEMM_SMEM (3 * A_ELEMS * 4)     // As + Bs0 + Bs1 = 202752 bytes

__global__ void __launch_bounds__(256)
gemm_tf32_kernel(const float* __restrict__ A,
                 const float* __restrict__ B,
                 float* __restrict__ T,
                 float* __restrict__ hn,
                 int relu_a) {
    extern __shared__ float sm[];
    float* As  = sm;
    float* Bs0 = sm + A_ELEMS;
    float* Bs1 = Bs0 + A_ELEMS;

    const int tid = threadIdx.x;
    const int m0 = blockIdx.y * 128;
    const int t0 = (blockIdx.x == 0) ? 0 : 9;
    const int t1 = (blockIdx.x == 0) ? 9 : NTILES;

    const uint32_t sb = smem_u32(sm);

    // ---- A tile: load, optional relu, fp32->tf32, store to smem (once)
    for (int i = tid; i < 128 * 32; i += 256) {
        int r = i >> 5, c4 = i & 31;
        float4 v = *reinterpret_cast<const float4*>(A + (size_t)(m0 + r) * DIMS + c4 * 4);
        if (relu_a) {
            v.x = fmaxf(v.x, 0.f); v.y = fmaxf(v.y, 0.f);
            v.z = fmaxf(v.z, 0.f); v.w = fmaxf(v.w, 0.f);
        }
        float4 w;
        w.x = wmma::__float_to_tf32(v.x);
        w.y = wmma::__float_to_tf32(v.y);
        w.z = wmma::__float_to_tf32(v.z);
        w.w = wmma::__float_to_tf32(v.w);
        *reinterpret_cast<float4*>(&As[r * LDSW + c4 * 4]) = w;
    }

    // ---- prefetch first B tile
    {
        const float* Bt = B + t0 * 128;
        uint32_t sbase = sb + (uint32_t)(A_ELEMS * 4);   // Bs0
        for (int i = tid; i < 128 * 32; i += 256) {
            int r = i >> 5, c4 = i & 31;
            cp_async16(sbase + (uint32_t)(r * LDSW + c4 * 4) * 4,
                       Bt + (size_t)r * NCOL + c4 * 4);
        }
        CP_COMMIT();
    }

    const int wid = tid >> 5;
    const int wm  = wid & 3;   // 4 warps over M (32 rows)
    const int wn  = wid >> 2;  // 2 warps over N (64 cols)

    for (int t = t0; t < t1; ++t) {
        float* Bs    = ((t - t0) & 1) ? Bs1 : Bs0;
        float* Bnext = ((t - t0) & 1) ? Bs0 : Bs1;

        if (t + 1 < t1) {
            const float* Bt = B + (t + 1) * 128;
            uint32_t sbase = sb + (uint32_t)((Bnext - sm) * 4);
            for (int i = tid; i < 128 * 32; i += 256) {
                int r = i >> 5, c4 = i & 31;
                cp_async16(sbase + (uint32_t)(r * LDSW + c4 * 4) * 4,
                           Bt + (size_t)r * NCOL + c4 * 4);
            }
            CP_COMMIT();
            CP_WAIT1();     // current tile's group done; next still in flight
        } else {
            CP_WAIT0();
        }
        __syncthreads();

        wmma::fragment<wmma::accumulator, 16, 16, 8, float> acc[2][4];
#pragma unroll
        for (int i = 0; i < 2; i++)
#pragma unroll
            for (int j = 0; j < 4; j++) wmma::fill_fragment(acc[i][j], 0.f);

#pragma unroll
        for (int k0 = 0; k0 < 128; k0 += 8) {
            wmma::fragment<wmma::matrix_a, 16, 16, 8, wmma::precision::tf32, wmma::row_major> af[2];
            wmma::fragment<wmma::matrix_b, 16, 16, 8, wmma::precision::tf32, wmma::row_major> bf[4];
#pragma unroll
            for (int i = 0; i < 2; i++)
                wmma::load_matrix_sync(af[i], As + (wm * 32 + i * 16) * LDSW + k0, LDSW);
#pragma unroll
            for (int j = 0; j < 4; j++)
                wmma::load_matrix_sync(bf[j], Bs + k0 * LDSW + wn * 64 + j * 16, LDSW);
#pragma unroll
            for (int i = 0; i < 2; i++)
#pragma unroll
                for (int j = 0; j < 4; j++)
                    wmma::mma_sync(acc[i][j], af[i], bf[j], acc[i][j]);
        }

        // direct writeout (rows are 64B-contiguous segments -> full sectors)
        float* outp;
        size_t ldc;
        if (t == 0) { outp = hn; ldc = DIMS; }
        else        { outp = T + (size_t)(t - 1) * 128; ldc = TCOL; }
#pragma unroll
        for (int i = 0; i < 2; i++)
#pragma unroll
            for (int j = 0; j < 4; j++)
                wmma::store_matrix_sync(outp + (size_t)(m0 + wm * 32 + i * 16) * ldc
                                             + wn * 64 + j * 16,
                                        acc[i][j], ldc, wmma::mem_row_major);
        __syncthreads();   // all warps done reading Bs before it is refilled
    }
}

// -------------------- scoring (applies relu to final h) ----------------------
__global__ void score_kernel(const float* __restrict__ h,
                             const int* __restrict__ heads,
                             const int* __restrict__ rels,
                             const int* __restrict__ tails,
                             const float* __restrict__ rel_emb,
                             const float* __restrict__ path_feat,
                             const int* __restrict__ task_idx,
                             const float* __restrict__ delta_w,
                             const float* __restrict__ lambda_logit,
                             const float* __restrict__ rule_init,
                             float* __restrict__ out) {
    int warp = (blockIdx.x * blockDim.x + threadIdx.x) >> 5;
    int lane = threadIdx.x & 31;
    if (warp >= NQUERY) return;
    int hh = heads[warp], rr = rels[warp], tt = tails[warp];
    float4 a = reinterpret_cast<const float4*>(h + (size_t)hh * DIMS)[lane];
    float4 r = reinterpret_cast<const float4*>(rel_emb + (size_t)rr * DIMS)[lane];
    float4 b = reinterpret_cast<const float4*>(h + (size_t)tt * DIMS)[lane];
    a.x = fmaxf(a.x, 0.f); a.y = fmaxf(a.y, 0.f); a.z = fmaxf(a.z, 0.f); a.w = fmaxf(a.w, 0.f);
    b.x = fmaxf(b.x, 0.f); b.y = fmaxf(b.y, 0.f); b.z = fmaxf(b.z, 0.f); b.w = fmaxf(b.w, 0.f);
    float s = a.x * r.x * b.x + a.y * r.y * b.y + a.z * r.z * b.z + a.w * r.w * b.w;
#pragma unroll
    for (int off = 16; off > 0; off >>= 1)
        s += __shfl_xor_sync(0xFFFFFFFFu, s, off);
    if (lane == 0) {
        int idx = task_idx[0];
        float sp = 0.f;
#pragma unroll
        for (int p = 0; p < PDIM; p++)
            sp += path_feat[warp * PDIM + p] * (rule_init[idx * PDIM + p] + delta_w[idx * PDIM + p]);
        float lam = 1.0f / (1.0f + __expf(-lambda_logit[idx]));
        out[warp] = lam * s + (1.0f - lam) * sp;
    }
}

// -------------------- launcher -----------------------------------------------
extern "C" void kernel_launch(void* const* d_in, const int* in_sizes, int n_in,
                              void* d_out, int out_size) {
    const int*   node_ids   = (const int*)d_in[0];
    const int*   edge_index = (const int*)d_in[1];
    const int*   edge_type  = (const int*)d_in[2];
    const int*   heads      = (const int*)d_in[3];
    const int*   rels       = (const int*)d_in[4];
    const int*   tails      = (const int*)d_in[5];
    const float* path_feat  = (const float*)d_in[6];
    const int*   task_idx   = (const int*)d_in[7];
    const float* entity_emb = (const float*)d_in[8];
    const float* rel_emb    = (const float*)d_in[9];
    const float* W_self     = (const float*)d_in[10];
    const float* W_rel      = (const float*)d_in[11];
    const float* delta_w    = (const float*)d_in[12];
    const float* lambda_lg  = (const float*)d_in[13];
    const float* rule_init  = (const float*)d_in[14];
    float*       out        = (float*)d_out;

    const int* src = edge_index;
    const int* dst = edge_index + NEDGE;

    float *hA, *hB, *T, *Bpack;
    cudaGetSymbolAddress((void**)&hA, g_hA);
    cudaGetSymbolAddress((void**)&hB, g_hB);
    cudaGetSymbolAddress((void**)&T, g_T);
    cudaGetSymbolAddress((void**)&Bpack, g_Bpack);

    const int TPB = 256;
    cudaFuncSetAttribute(gemm_tf32_kernel,
                         cudaFuncAttributeMaxDynamicSharedMemorySize, GEMM_SMEM);

    pack_weights_kernel<<<(NLAYER * DIMS * NCOL + TPB - 1) / TPB, TPB>>>(W_self, W_rel);
    gather_h_kernel<<<(NNODES * 32 + TPB - 1) / TPB, TPB>>>(node_ids, entity_emb);
    zero_cnt_kernel<<<(NNODES * NRELS + TPB - 1) / TPB, TPB>>>();
    count_kernel<<<(NEDGE + TPB - 1) / TPB, TPB>>>(dst, edge_type);

    float* h_cur = hA;
    float* h_nxt = hB;
    for (int l = 0; l < NLAYER; l++) {
        dim3 grid(2, MPAD / 128);
        gemm_tf32_kernel<<<grid, 256, GEMM_SMEM>>>(h_cur, Bpack + (size_t)l * DIMS * NCOL,
                                                   T, h_nxt, l > 0 ? 1 : 0);
        edge_agg_kernel<<<(NEDGE * 32 + TPB - 1) / TPB, TPB>>>(src, dst, edge_type, h_nxt);
        float* tmp = h_cur; h_cur = h_nxt; h_nxt = tmp;
    }

    score_kernel<<<(NQUERY * 32 + TPB - 1) / TPB, TPB>>>(
        h_cur, heads, rels, tails, rel_emb, path_feat, task_idx,
        delta_w, lambda_lg, rule_init, out);
}

// round 5
// speedup vs baseline: 2.7257x; 1.6165x over previous
#include <cuda_runtime.h>
#include <cuda_fp16.h>
#include <mma.h>
#include <cstdint>

#define NNODES 50000
#define MPAD   50048            // 391 * 128
#define NRELS  16
#define DIMS   128
#define NLAYER 2
#define NEDGE  600000
#define NQUERY 8192
#define PDIM   5
#define NCOL   (DIMS * (NRELS + 1))   // 2176 weight cols: [self | rel0..rel15]
#define TCOL   (DIMS * NRELS)         // 2048 cols in T
#define NTILES (NCOL / 128)           // 17

// -------------------- scratch ------------------------------------------------
__device__ float  g_hA[(size_t)MPAD * DIMS];
__device__ float  g_hB[(size_t)MPAD * DIMS];
__device__ __half g_T[(size_t)MPAD * TCOL];          // fp16 transformed features
__device__ float  g_Bpack[NLAYER][DIMS * NCOL];      // [K=128][N=2176] tf32 bits
__device__ int    g_cnt[NNODES * NRELS];

// -------------------- helpers ------------------------------------------------
__device__ __forceinline__ uint32_t smem_u32(const void* p) {
    uint32_t a;
    asm("{ .reg .u64 t; cvta.to.shared.u64 t, %1; cvt.u32.u64 %0, t; }" : "=r"(a) : "l"(p));
    return a;
}
__device__ __forceinline__ void red_add_v4(float* addr, float x, float y, float z, float w) {
    asm volatile("red.global.add.v4.f32 [%0], {%1, %2, %3, %4};"
                 :: "l"(addr), "f"(x), "f"(y), "f"(z), "f"(w) : "memory");
}
__device__ __forceinline__ void cp_async16(uint32_t saddr, const void* g) {
    asm volatile("cp.async.ca.shared.global [%0], [%1], 16;" :: "r"(saddr), "l"(g));
}
#define CP_COMMIT() asm volatile("cp.async.commit_group;")
#define CP_WAIT0()  asm volatile("cp.async.wait_group 0;")
#define CP_WAIT1()  asm volatile("cp.async.wait_group 1;")

__device__ __forceinline__ uint32_t f2tf32(float f) {
    return __float_as_uint(nvcuda::wmma::__float_to_tf32(f));
}
__device__ __forceinline__ void mma_tf32(float c[4], const uint32_t a[4], const uint32_t b[2]) {
    asm volatile(
        "mma.sync.aligned.m16n8k8.row.col.f32.tf32.tf32.f32 "
        "{%0,%1,%2,%3}, {%4,%5,%6,%7}, {%8,%9}, {%0,%1,%2,%3};"
        : "+f"(c[0]), "+f"(c[1]), "+f"(c[2]), "+f"(c[3])
        : "r"(a[0]), "r"(a[1]), "r"(a[2]), "r"(a[3]), "r"(b[0]), "r"(b[1]));
}

// -------------------- small kernels -----------------------------------------
__global__ void pack_weights_kernel(const float* __restrict__ Wself,
                                    const float* __restrict__ Wrel) {
    int idx = blockIdx.x * blockDim.x + threadIdx.x;
    const int total = NLAYER * DIMS * NCOL;
    if (idx >= total) return;
    int l   = idx / (DIMS * NCOL);
    int rem = idx - l * (DIMS * NCOL);
    int k   = rem / NCOL;
    int n   = rem - k * NCOL;
    float v;
    if (n < DIMS) {
        v = Wself[(l * DIMS + k) * DIMS + n];
    } else {
        int r = (n - DIMS) >> 7;
        int e = (n - DIMS) & 127;
        v = Wrel[(((size_t)(l * NRELS + r) * DIMS) + k) * DIMS + e];
    }
    g_Bpack[l][k * NCOL + n] = __uint_as_float(f2tf32(v));
}

__global__ void zero_cnt_kernel() {
    int i = blockIdx.x * blockDim.x + threadIdx.x;
    if (i < NNODES * NRELS) g_cnt[i] = 0;
}

__global__ void count_kernel(const int* __restrict__ dst, const int* __restrict__ et) {
    int e = blockIdx.x * blockDim.x + threadIdx.x;
    if (e >= NEDGE) return;
    atomicAdd(&g_cnt[dst[e] * NRELS + et[e]], 1);
}

// one warp per edge: read fp16 T[src, rel-block], scale by 1/cnt, RED into hn[dst]
__global__ void edge_agg_kernel(const int* __restrict__ src,
                                const int* __restrict__ dst,
                                const int* __restrict__ et,
                                float* __restrict__ hn) {
    int warp = (blockIdx.x * blockDim.x + threadIdx.x) >> 5;
    int lane = threadIdx.x & 31;
    if (warp >= NEDGE) return;
    int s = src[warp];
    int d = dst[warp];
    int r = et[warp];
    int c = g_cnt[d * NRELS + r];
    float we = 1.0f / (float)c;
    const uint2* row = reinterpret_cast<const uint2*>(g_T + (size_t)s * TCOL + r * DIMS);
    uint2 u = row[lane];
    __half2 p0 = *reinterpret_cast<__half2*>(&u.x);
    __half2 p1 = *reinterpret_cast<__half2*>(&u.y);
    float2 f0 = __half22float2(p0);
    float2 f1 = __half22float2(p1);
    red_add_v4(hn + (size_t)d * DIMS + lane * 4,
               f0.x * we, f0.y * we, f1.x * we, f1.y * we);
}

// -------------------- manual tf32 GEMM ---------------------------------------
// Block 256 thr, tile M=128; loops over 128-col N tiles. A staged once (tf32),
// B double-buffered cp.async. mma.sync.m16n8k8; conflict-free smem patterns.
#define LDSA 132
#define LDSB 136
#define SM_AW (128 * LDSA)                 // words
#define SM_BW (128 * LDSB)
#define GEMM_SMEM ((SM_AW + 2 * SM_BW) * 4)   // 206848 bytes

__global__ void __launch_bounds__(256)
gemm_kernel(const float* __restrict__ A,        // [MPAD,128] (layer>=2)
            const int* __restrict__ nid,        // gather ids (layer 1) or null
            const float* __restrict__ emb,      // entity emb (layer 1)
            const float* __restrict__ B,        // packed tf32 [128, NCOL]
            __half* __restrict__ T,
            float* __restrict__ hn,
            int relu_a) {
    extern __shared__ float sm[];
    uint32_t* AsU  = reinterpret_cast<uint32_t*>(sm);
    uint32_t* Bs0U = AsU + SM_AW;
    uint32_t* Bs1U = Bs0U + SM_BW;
    const uint32_t sb = smem_u32(sm);

    const int tid = threadIdx.x;
    const int m0 = blockIdx.y * 128;
    const int t0 = (blockIdx.x == 0) ? 0 : 9;
    const int t1 = (blockIdx.x == 0) ? 9 : NTILES;

    // ---- stage A (gather / relu / tf32 convert), once
    for (int i = tid; i < 128 * 32; i += 256) {
        int r = i >> 5, c4 = i & 31;
        const float* arow;
        if (nid) {
            int m = m0 + r;
            int id = nid[m < NNODES ? m : NNODES - 1];
            arow = emb + (size_t)id * DIMS;
        } else {
            arow = A + (size_t)(m0 + r) * DIMS;
        }
        float4 v = reinterpret_cast<const float4*>(arow)[c4];
        if (relu_a) {
            v.x = fmaxf(v.x, 0.f); v.y = fmaxf(v.y, 0.f);
            v.z = fmaxf(v.z, 0.f); v.w = fmaxf(v.w, 0.f);
        }
        uint4 w = make_uint4(f2tf32(v.x), f2tf32(v.y), f2tf32(v.z), f2tf32(v.w));
        *reinterpret_cast<uint4*>(&AsU[r * LDSA + c4 * 4]) = w;
    }

    // ---- prefetch first B tile into Bs0
    {
        const float* Bt = B + t0 * 128;
        uint32_t sbase = sb + SM_AW * 4;
        for (int i = tid; i < 128 * 32; i += 256) {
            int r = i >> 5, c4 = i & 31;
            cp_async16(sbase + (uint32_t)(r * LDSB + c4 * 4) * 4,
                       Bt + (size_t)r * NCOL + c4 * 4);
        }
        CP_COMMIT();
    }

    const int wid  = tid >> 5;
    const int wm   = wid & 3;          // 4 warp rows (32 M each)
    const int wn   = wid >> 2;         // 2 warp cols (64 N each)
    const int lane = tid & 31;
    const int qid  = lane >> 2;        // 0..7
    const int rid  = lane & 3;         // 0..3

    for (int t = t0; t < t1; ++t) {
        uint32_t* Bs    = ((t - t0) & 1) ? Bs1U : Bs0U;
        uint32_t* Bnext = ((t - t0) & 1) ? Bs0U : Bs1U;

        if (t + 1 < t1) {
            const float* Bt = B + (t + 1) * 128;
            uint32_t sbase = sb + (uint32_t)((Bnext - AsU) * 4);
            for (int i = tid; i < 128 * 32; i += 256) {
                int r = i >> 5, c4 = i & 31;
                cp_async16(sbase + (uint32_t)(r * LDSB + c4 * 4) * 4,
                           Bt + (size_t)r * NCOL + c4 * 4);
            }
            CP_COMMIT();
            CP_WAIT1();
        } else {
            CP_WAIT0();
        }
        __syncthreads();

        float c[2][8][4];
#pragma unroll
        for (int im = 0; im < 2; im++)
#pragma unroll
            for (int jn = 0; jn < 8; jn++)
#pragma unroll
                for (int q = 0; q < 4; q++) c[im][jn][q] = 0.f;

#pragma unroll
        for (int kk = 0; kk < 16; kk++) {
            const int kb = kk * 8;
            uint32_t a[2][4];
#pragma unroll
            for (int im = 0; im < 2; im++) {
                int rbase = wm * 32 + im * 16;
                a[im][0] = AsU[(rbase + qid) * LDSA + kb + rid];
                a[im][1] = AsU[(rbase + qid + 8) * LDSA + kb + rid];
                a[im][2] = AsU[(rbase + qid) * LDSA + kb + rid + 4];
                a[im][3] = AsU[(rbase + qid + 8) * LDSA + kb + rid + 4];
            }
            uint32_t b[8][2];
#pragma unroll
            for (int jn = 0; jn < 8; jn++) {
                int nb = wn * 64 + jn * 8 + qid;
                b[jn][0] = Bs[(kb + rid) * LDSB + nb];
                b[jn][1] = Bs[(kb + rid + 4) * LDSB + nb];
            }
#pragma unroll
            for (int im = 0; im < 2; im++)
#pragma unroll
                for (int jn = 0; jn < 8; jn++)
                    mma_tf32(c[im][jn], a[im], b[jn]);
        }

        // ---- in-register epilogue
        if (t == 0) {
#pragma unroll
            for (int im = 0; im < 2; im++) {
                int row = m0 + wm * 32 + im * 16 + qid;
#pragma unroll
                for (int jn = 0; jn < 8; jn++) {
                    int col = wn * 64 + jn * 8 + 2 * rid;
                    *reinterpret_cast<float2*>(hn + (size_t)row * DIMS + col)
                        = make_float2(c[im][jn][0], c[im][jn][1]);
                    *reinterpret_cast<float2*>(hn + (size_t)(row + 8) * DIMS + col)
                        = make_float2(c[im][jn][2], c[im][jn][3]);
                }
            }
        } else {
            int cbase = (t - 1) * 128 + wn * 64;
#pragma unroll
            for (int im = 0; im < 2; im++) {
                int row = m0 + wm * 32 + im * 16 + qid;
#pragma unroll
                for (int jn = 0; jn < 8; jn++) {
                    int col = cbase + jn * 8 + 2 * rid;
                    *reinterpret_cast<__half2*>(T + (size_t)row * TCOL + col)
                        = __floats2half2_rn(c[im][jn][0], c[im][jn][1]);
                    *reinterpret_cast<__half2*>(T + (size_t)(row + 8) * TCOL + col)
                        = __floats2half2_rn(c[im][jn][2], c[im][jn][3]);
                }
            }
        }
        __syncthreads();   // all warps done with Bs before it is refilled
    }
}

// -------------------- scoring (relu fused) -----------------------------------
__global__ void score_kernel(const float* __restrict__ h,
                             const int* __restrict__ heads,
                             const int* __restrict__ rels,
                             const int* __restrict__ tails,
                             const float* __restrict__ rel_emb,
                             const float* __restrict__ path_feat,
                             const int* __restrict__ task_idx,
                             const float* __restrict__ delta_w,
                             const float* __restrict__ lambda_logit,
                             const float* __restrict__ rule_init,
                             float* __restrict__ out) {
    int warp = (blockIdx.x * blockDim.x + threadIdx.x) >> 5;
    int lane = threadIdx.x & 31;
    if (warp >= NQUERY) return;
    int hh = heads[warp], rr = rels[warp], tt = tails[warp];
    float4 a = reinterpret_cast<const float4*>(h + (size_t)hh * DIMS)[lane];
    float4 r = reinterpret_cast<const float4*>(rel_emb + (size_t)rr * DIMS)[lane];
    float4 b = reinterpret_cast<const float4*>(h + (size_t)tt * DIMS)[lane];
    a.x = fmaxf(a.x, 0.f); a.y = fmaxf(a.y, 0.f); a.z = fmaxf(a.z, 0.f); a.w = fmaxf(a.w, 0.f);
    b.x = fmaxf(b.x, 0.f); b.y = fmaxf(b.y, 0.f); b.z = fmaxf(b.z, 0.f); b.w = fmaxf(b.w, 0.f);
    float s = a.x * r.x * b.x + a.y * r.y * b.y + a.z * r.z * b.z + a.w * r.w * b.w;
#pragma unroll
    for (int off = 16; off > 0; off >>= 1)
        s += __shfl_xor_sync(0xFFFFFFFFu, s, off);
    if (lane == 0) {
        int idx = task_idx[0];
        float sp = 0.f;
#pragma unroll
        for (int p = 0; p < PDIM; p++)
            sp += path_feat[warp * PDIM + p] * (rule_init[idx * PDIM + p] + delta_w[idx * PDIM + p]);
        float lam = 1.0f / (1.0f + __expf(-lambda_logit[idx]));
        out[warp] = lam * s + (1.0f - lam) * sp;
    }
}

// -------------------- launcher -----------------------------------------------
extern "C" void kernel_launch(void* const* d_in, const int* in_sizes, int n_in,
                              void* d_out, int out_size) {
    const int*   node_ids   = (const int*)d_in[0];
    const int*   edge_index = (const int*)d_in[1];
    const int*   edge_type  = (const int*)d_in[2];
    const int*   heads      = (const int*)d_in[3];
    const int*   rels       = (const int*)d_in[4];
    const int*   tails      = (const int*)d_in[5];
    const float* path_feat  = (const float*)d_in[6];
    const int*   task_idx   = (const int*)d_in[7];
    const float* entity_emb = (const float*)d_in[8];
    const float* rel_emb    = (const float*)d_in[9];
    const float* W_self     = (const float*)d_in[10];
    const float* W_rel      = (const float*)d_in[11];
    const float* delta_w    = (const float*)d_in[12];
    const float* lambda_lg  = (const float*)d_in[13];
    const float* rule_init  = (const float*)d_in[14];
    float*       out        = (float*)d_out;

    const int* src = edge_index;
    const int* dst = edge_index + NEDGE;

    float *hA, *hB, *Bpack;
    __half* T;
    cudaGetSymbolAddress((void**)&hA, g_hA);
    cudaGetSymbolAddress((void**)&hB, g_hB);
    cudaGetSymbolAddress((void**)&T, g_T);
    cudaGetSymbolAddress((void**)&Bpack, g_Bpack);

    const int TPB = 256;
    cudaFuncSetAttribute(gemm_kernel,
                         cudaFuncAttributeMaxDynamicSharedMemorySize, GEMM_SMEM);

    pack_weights_kernel<<<(NLAYER * DIMS * NCOL + TPB - 1) / TPB, TPB>>>(W_self, W_rel);
    zero_cnt_kernel<<<(NNODES * NRELS + TPB - 1) / TPB, TPB>>>();
    count_kernel<<<(NEDGE + TPB - 1) / TPB, TPB>>>(dst, edge_type);

    dim3 grid(2, MPAD / 128);
    // layer 1: gather A from entity_emb via node_ids
    gemm_kernel<<<grid, 256, GEMM_SMEM>>>(nullptr, node_ids, entity_emb,
                                          Bpack, T, hB, 0);
    edge_agg_kernel<<<(NEDGE * 32 + TPB - 1) / TPB, TPB>>>(src, dst, edge_type, hB);
    // layer 2: A = relu(hB)
    gemm_kernel<<<grid, 256, GEMM_SMEM>>>(hB, nullptr, nullptr,
                                          Bpack + (size_t)DIMS * NCOL, T, hA, 1);
    edge_agg_kernel<<<(NEDGE * 32 + TPB - 1) / TPB, TPB>>>(src, dst, edge_type, hA);

    score_kernel<<<(NQUERY * 32 + TPB - 1) / TPB, TPB>>>(
        hA, heads, rels, tails, rel_emb, path_feat, task_idx,
        delta_w, lambda_lg, rule_init, out);
}

// round 6
// speedup vs baseline: 2.8497x; 1.0455x over previous
#include <cuda_runtime.h>
#include <cuda_fp16.h>
#include <mma.h>
#include <cstdint>

#define NNODES 50000
#define MPAD   50048            // 391 * 128
#define NRELS  16
#define DIMS   128
#define NLAYER 2
#define NEDGE  600000
#define NQUERY 8192
#define PDIM   5
#define NCOL   (DIMS * (NRELS + 1))   // 2176 weight cols: [self | rel0..rel15]
#define TCOL   (DIMS * NRELS)         // 2048 cols in T
#define NTILES (NCOL / 128)           // 17
#define TILE_WORDS (128 * 128)        // 16384 floats per B tile (fragment-major)

// -------------------- scratch ------------------------------------------------
__device__ float  g_hA[(size_t)MPAD * DIMS];
__device__ float  g_hB[(size_t)MPAD * DIMS];
__device__ __half g_T[(size_t)MPAD * TCOL];
// fragment-major packed weights: [layer][tile][cj(16)][kp(8)][lane(32)][q(4)]
__device__ float  g_Bpack[NLAYER][(size_t)NCOL * DIMS];
__device__ int    g_cnt[NNODES * NRELS];

// -------------------- helpers ------------------------------------------------
__device__ __forceinline__ uint32_t smem_u32(const void* p) {
    uint32_t a;
    asm("{ .reg .u64 t; cvta.to.shared.u64 t, %1; cvt.u32.u64 %0, t; }" : "=r"(a) : "l"(p));
    return a;
}
__device__ __forceinline__ void red_add_v4(float* addr, float x, float y, float z, float w) {
    asm volatile("red.global.add.v4.f32 [%0], {%1, %2, %3, %4};"
                 :: "l"(addr), "f"(x), "f"(y), "f"(z), "f"(w) : "memory");
}
__device__ __forceinline__ void cp_async16(uint32_t saddr, const void* g) {
    asm volatile("cp.async.ca.shared.global [%0], [%1], 16;" :: "r"(saddr), "l"(g));
}
#define CP_COMMIT() asm volatile("cp.async.commit_group;")
#define CP_WAIT0()  asm volatile("cp.async.wait_group 0;")
#define CP_WAIT1()  asm volatile("cp.async.wait_group 1;")

__device__ __forceinline__ uint32_t f2tf32(float f) {
    return __float_as_uint(nvcuda::wmma::__float_to_tf32(f));
}
__device__ __forceinline__ void mma_tf32(float c[4], float4 a, float b0, float b1) {
    asm volatile(
        "mma.sync.aligned.m16n8k8.row.col.f32.tf32.tf32.f32 "
        "{%0,%1,%2,%3}, {%4,%5,%6,%7}, {%8,%9}, {%0,%1,%2,%3};"
        : "+f"(c[0]), "+f"(c[1]), "+f"(c[2]), "+f"(c[3])
        : "r"(__float_as_uint(a.x)), "r"(__float_as_uint(a.y)),
          "r"(__float_as_uint(a.z)), "r"(__float_as_uint(a.w)),
          "r"(__float_as_uint(b0)), "r"(__float_as_uint(b1)));
}

// -------------------- small kernels -----------------------------------------
// pack weights into fragment-major tf32 layout (see header comment)
__global__ void pack_weights_kernel(const float* __restrict__ Wself,
                                    const float* __restrict__ Wrel) {
    int idx = blockIdx.x * blockDim.x + threadIdx.x;
    const int per_layer = NCOL * DIMS;          // 278528
    const int total = NLAYER * per_layer;
    if (idx >= total) return;
    int l   = idx / per_layer;
    int rem = idx - l * per_layer;
    int q    = rem & 3;
    int f4i  = rem >> 2;
    int lane = f4i & 31;
    int kp   = (f4i >> 5) & 7;
    int cj   = (f4i >> 8) & 15;
    int t    = f4i >> 12;
    int qid = lane >> 2, rid = lane & 3;
    int k = kp * 16 + (q >> 1) * 8 + (q & 1) * 4 + rid;     // 0..127
    int n = t * 128 + cj * 8 + qid;                          // 0..2175
    float v;
    if (n < DIMS) {
        v = Wself[(l * DIMS + k) * DIMS + n];
    } else {
        int r = (n - DIMS) >> 7;
        int e = (n - DIMS) & 127;
        v = Wrel[(((size_t)(l * NRELS + r) * DIMS) + k) * DIMS + e];
    }
    g_Bpack[l][rem] = __uint_as_float(f2tf32(v));
}

__global__ void zero_cnt_kernel() {
    int i = blockIdx.x * blockDim.x + threadIdx.x;
    if (i < NNODES * NRELS) g_cnt[i] = 0;
}

__global__ void count_kernel(const int* __restrict__ dst, const int* __restrict__ et) {
    int e = blockIdx.x * blockDim.x + threadIdx.x;
    if (e >= NEDGE) return;
    atomicAdd(&g_cnt[dst[e] * NRELS + et[e]], 1);
}

__global__ void edge_agg_kernel(const int* __restrict__ src,
                                const int* __restrict__ dst,
                                const int* __restrict__ et,
                                float* __restrict__ hn) {
    int warp = (blockIdx.x * blockDim.x + threadIdx.x) >> 5;
    int lane = threadIdx.x & 31;
    if (warp >= NEDGE) return;
    int s = src[warp];
    int d = dst[warp];
    int r = et[warp];
    int c = g_cnt[d * NRELS + r];
    float we = 1.0f / (float)c;
    const uint2* row = reinterpret_cast<const uint2*>(g_T + (size_t)s * TCOL + r * DIMS);
    uint2 u = row[lane];
    __half2 p0 = *reinterpret_cast<__half2*>(&u.x);
    __half2 p1 = *reinterpret_cast<__half2*>(&u.y);
    float2 f0 = __half22float2(p0);
    float2 f1 = __half22float2(p1);
    red_add_v4(hn + (size_t)d * DIMS + lane * 4,
               f0.x * we, f0.y * we, f1.x * we, f1.y * we);
}

// -------------------- fragment-major tf32 GEMM --------------------------------
// 512 threads (16 warps, 4x4). M tile 128, N tile 128, loops over N tiles.
// A staged once and permuted to fragment-major; B arrives fragment-major via
// cp.async double buffer. All mainloop smem reads are LDS.128 conflict-free.
// smem floats: A_frag [0, 16384) | Bs0 [16384, 32768) | Bs1 [32768, 49152)
#define GEMM_SMEM (49152 * 4)

__global__ void __launch_bounds__(512)
gemm_kernel(const float* __restrict__ A,        // [MPAD,128] (layer 2)
            const int* __restrict__ nid,        // gather ids (layer 1) or null
            const float* __restrict__ emb,      // entity emb (layer 1)
            const float* __restrict__ B,        // fragment-major tf32
            __half* __restrict__ T,
            float* __restrict__ hn,
            int relu_a) {
    extern __shared__ float sm[];
    float4* AsF4  = reinterpret_cast<float4*>(sm);            // 4096 float4
    float*  Bs0   = sm + 16384;
    float*  Bs1   = sm + 32768;
    float*  scr   = Bs0;                                      // stage-1 scratch
    const uint32_t sb = smem_u32(sm);

    const int tid = threadIdx.x;
    const int m0 = blockIdx.y * 128;
    const int t0 = (blockIdx.x == 0) ? 0 : 9;
    const int t1 = (blockIdx.x == 0) ? 9 : NTILES;

    // ---- stage 1: A tile row-major into scratch (coalesced), tf32-converted
    for (int i = tid; i < 128 * 32; i += 512) {
        int r = i >> 5, c4 = i & 31;
        const float* arow;
        if (nid) {
            int m = m0 + r;
            int id = nid[m < NNODES ? m : NNODES - 1];
            arow = emb + (size_t)id * DIMS;
        } else {
            arow = A + (size_t)(m0 + r) * DIMS;
        }
        float4 v = reinterpret_cast<const float4*>(arow)[c4];
        if (relu_a) {
            v.x = fmaxf(v.x, 0.f); v.y = fmaxf(v.y, 0.f);
            v.z = fmaxf(v.z, 0.f); v.w = fmaxf(v.w, 0.f);
        }
        float4 w;
        w.x = __uint_as_float(f2tf32(v.x));
        w.y = __uint_as_float(f2tf32(v.y));
        w.z = __uint_as_float(f2tf32(v.z));
        w.w = __uint_as_float(f2tf32(v.w));
        *reinterpret_cast<float4*>(&scr[r * 128 + c4 * 4]) = w;
    }
    __syncthreads();

    // ---- stage 2: permute A to fragment-major
    // item = (bi*16 + kk)*32 + lane ; float4 {A[r0,k0], A[r0+8,k0], A[r0,k0+4], A[r0+8,k0+4]}
    {
        float4 tmp[8];
#pragma unroll
        for (int it = 0; it < 8; it++) {
            int item = tid + it * 512;
            int bi   = item >> 9;
            int remi = item & 511;
            int kk   = remi >> 5;
            int ln   = remi & 31;
            int r0 = bi * 16 + (ln >> 2);
            int k0 = kk * 8 + (ln & 3);
            tmp[it] = make_float4(scr[r0 * 128 + k0],       scr[(r0 + 8) * 128 + k0],
                                  scr[r0 * 128 + k0 + 4],   scr[(r0 + 8) * 128 + k0 + 4]);
        }
        __syncthreads();    // done reading scratch before A_frag writes? (disjoint) -- and before B prefetch reuses it
#pragma unroll
        for (int it = 0; it < 8; it++) AsF4[tid + it * 512] = tmp[it];
    }
    __syncthreads();

    // ---- prefetch first B tile into Bs0 (fragment-major, contiguous 64 KB)
    {
        const float* Bt = B + (size_t)t0 * TILE_WORDS;
        uint32_t sbase = sb + 16384u * 4u;
        for (int i = tid; i < 4096; i += 512)
            cp_async16(sbase + (uint32_t)i * 16u, Bt + i * 4);
        CP_COMMIT();
    }

    const int wid  = tid >> 5;
    const int wm   = wid & 3;          // 4 warp rows (32 M each)
    const int wn   = wid >> 2;         // 4 warp cols (32 N each)
    const int lane = tid & 31;
    const int qid  = lane >> 2;
    const int rid  = lane & 3;

    for (int t = t0; t < t1; ++t) {
        float* Bs    = ((t - t0) & 1) ? Bs1 : Bs0;
        float* Bnext = ((t - t0) & 1) ? Bs0 : Bs1;

        if (t + 1 < t1) {
            const float* Bt = B + (size_t)(t + 1) * TILE_WORDS;
            uint32_t sbase = sb + (uint32_t)((Bnext - sm) * 4);
            for (int i = tid; i < 4096; i += 512)
                cp_async16(sbase + (uint32_t)i * 16u, Bt + i * 4);
            CP_COMMIT();
            CP_WAIT1();
        } else {
            CP_WAIT0();
        }
        __syncthreads();

        const float4* BsF4 = reinterpret_cast<const float4*>(Bs);
        float c[2][4][4];
#pragma unroll
        for (int im = 0; im < 2; im++)
#pragma unroll
            for (int jn = 0; jn < 4; jn++)
#pragma unroll
                for (int q = 0; q < 4; q++) c[im][jn][q] = 0.f;

#pragma unroll
        for (int kp = 0; kp < 8; kp++) {
            float4 bf[4];
#pragma unroll
            for (int jn = 0; jn < 4; jn++)
                bf[jn] = BsF4[(((wn * 4 + jn) * 8 + kp) << 5) + lane];
#pragma unroll
            for (int half = 0; half < 2; half++) {
                int kk = kp * 2 + half;
                float4 af[2];
                af[0] = AsF4[(((wm * 2 + 0) * 16 + kk) << 5) + lane];
                af[1] = AsF4[(((wm * 2 + 1) * 16 + kk) << 5) + lane];
#pragma unroll
                for (int im = 0; im < 2; im++)
#pragma unroll
                    for (int jn = 0; jn < 4; jn++) {
                        float b0 = half ? bf[jn].z : bf[jn].x;
                        float b1 = half ? bf[jn].w : bf[jn].y;
                        mma_tf32(c[im][jn], af[im], b0, b1);
                    }
            }
        }

        // ---- in-register epilogue
        if (t == 0) {
#pragma unroll
            for (int im = 0; im < 2; im++) {
                int row = m0 + wm * 32 + im * 16 + qid;
#pragma unroll
                for (int jn = 0; jn < 4; jn++) {
                    int col = wn * 32 + jn * 8 + 2 * rid;
                    *reinterpret_cast<float2*>(hn + (size_t)row * DIMS + col)
                        = make_float2(c[im][jn][0], c[im][jn][1]);
                    *reinterpret_cast<float2*>(hn + (size_t)(row + 8) * DIMS + col)
                        = make_float2(c[im][jn][2], c[im][jn][3]);
                }
            }
        } else {
            int cbase = (t - 1) * 128 + wn * 32;
#pragma unroll
            for (int im = 0; im < 2; im++) {
                int row = m0 + wm * 32 + im * 16 + qid;
#pragma unroll
                for (int jn = 0; jn < 4; jn++) {
                    int col = cbase + jn * 8 + 2 * rid;
                    *reinterpret_cast<__half2*>(T + (size_t)row * TCOL + col)
                        = __floats2half2_rn(c[im][jn][0], c[im][jn][1]);
                    *reinterpret_cast<__half2*>(T + (size_t)(row + 8) * TCOL + col)
                        = __floats2half2_rn(c[im][jn][2], c[im][jn][3]);
                }
            }
        }
        __syncthreads();   // all warps done with Bs before refill
    }
}

// -------------------- scoring (relu fused) -----------------------------------
__global__ void score_kernel(const float* __restrict__ h,
                             const int* __restrict__ heads,
                             const int* __restrict__ rels,
                             const int* __restrict__ tails,
                             const float* __restrict__ rel_emb,
                             const float* __restrict__ path_feat,
                             const int* __restrict__ task_idx,
                             const float* __restrict__ delta_w,
                             const float* __restrict__ lambda_logit,
                             const float* __restrict__ rule_init,
                             float* __restrict__ out) {
    int warp = (blockIdx.x * blockDim.x + threadIdx.x) >> 5;
    int lane = threadIdx.x & 31;
    if (warp >= NQUERY) return;
    int hh = heads[warp], rr = rels[warp], tt = tails[warp];
    float4 a = reinterpret_cast<const float4*>(h + (size_t)hh * DIMS)[lane];
    float4 r = reinterpret_cast<const float4*>(rel_emb + (size_t)rr * DIMS)[lane];
    float4 b = reinterpret_cast<const float4*>(h + (size_t)tt * DIMS)[lane];
    a.x = fmaxf(a.x, 0.f); a.y = fmaxf(a.y, 0.f); a.z = fmaxf(a.z, 0.f); a.w = fmaxf(a.w, 0.f);
    b.x = fmaxf(b.x, 0.f); b.y = fmaxf(b.y, 0.f); b.z = fmaxf(b.z, 0.f); b.w = fmaxf(b.w, 0.f);
    float s = a.x * r.x * b.x + a.y * r.y * b.y + a.z * r.z * b.z + a.w * r.w * b.w;
#pragma unroll
    for (int off = 16; off > 0; off >>= 1)
        s += __shfl_xor_sync(0xFFFFFFFFu, s, off);
    if (lane == 0) {
        int idx = task_idx[0];
        float sp = 0.f;
#pragma unroll
        for (int p = 0; p < PDIM; p++)
            sp += path_feat[warp * PDIM + p] * (rule_init[idx * PDIM + p] + delta_w[idx * PDIM + p]);
        float lam = 1.0f / (1.0f + __expf(-lambda_logit[idx]));
        out[warp] = lam * s + (1.0f - lam) * sp;
    }
}

// -------------------- launcher -----------------------------------------------
extern "C" void kernel_launch(void* const* d_in, const int* in_sizes, int n_in,
                              void* d_out, int out_size) {
    const int*   node_ids   = (const int*)d_in[0];
    const int*   edge_index = (const int*)d_in[1];
    const int*   edge_type  = (const int*)d_in[2];
    const int*   heads      = (const int*)d_in[3];
    const int*   rels       = (const int*)d_in[4];
    const int*   tails      = (const int*)d_in[5];
    const float* path_feat  = (const float*)d_in[6];
    const int*   task_idx   = (const int*)d_in[7];
    const float* entity_emb = (const float*)d_in[8];
    const float* rel_emb    = (const float*)d_in[9];
    const float* W_self     = (const float*)d_in[10];
    const float* W_rel      = (const float*)d_in[11];
    const float* delta_w    = (const float*)d_in[12];
    const float* lambda_lg  = (const float*)d_in[13];
    const float* rule_init  = (const float*)d_in[14];
    float*       out        = (float*)d_out;

    const int* src = edge_index;
    const int* dst = edge_index + NEDGE;

    float *hA, *hB, *Bpack;
    __half* T;
    cudaGetSymbolAddress((void**)&hA, g_hA);
    cudaGetSymbolAddress((void**)&hB, g_hB);
    cudaGetSymbolAddress((void**)&T, g_T);
    cudaGetSymbolAddress((void**)&Bpack, g_Bpack);

    const int TPB = 256;
    cudaFuncSetAttribute(gemm_kernel,
                         cudaFuncAttributeMaxDynamicSharedMemorySize, GEMM_SMEM);

    pack_weights_kernel<<<(NLAYER * NCOL * DIMS + TPB - 1) / TPB, TPB>>>(W_self, W_rel);
    zero_cnt_kernel<<<(NNODES * NRELS + TPB - 1) / TPB, TPB>>>();
    count_kernel<<<(NEDGE + TPB - 1) / TPB, TPB>>>(dst, edge_type);

    dim3 grid(2, MPAD / 128);
    // layer 1: gather A from entity_emb via node_ids
    gemm_kernel<<<grid, 512, GEMM_SMEM>>>(nullptr, node_ids, entity_emb,
                                          Bpack, T, hB, 0);
    edge_agg_kernel<<<(NEDGE * 32 + TPB - 1) / TPB, TPB>>>(src, dst, edge_type, hB);
    // layer 2: A = relu(hB)
    gemm_kernel<<<grid, 512, GEMM_SMEM>>>(hB, nullptr, nullptr,
                                          Bpack + (size_t)NCOL * DIMS, T, hA, 1);
    edge_agg_kernel<<<(NEDGE * 32 + TPB - 1) / TPB, TPB>>>(src, dst, edge_type, hA);

    score_kernel<<<(NQUERY * 32 + TPB - 1) / TPB, TPB>>>(
        hA, heads, rels, tails, rel_emb, path_feat, task_idx,
        delta_w, lambda_lg, rule_init, out);
}

// round 7
// speedup vs baseline: 3.7529x; 1.3170x over previous
#include <cuda_runtime.h>
#include <cuda_fp16.h>
#include <cstdint>

#define NNODES 50000
#define MPAD   50048            // 391 * 128
#define NRELS  16
#define DIMS   128
#define NLAYER 2
#define NEDGE  600000
#define NQUERY 8192
#define PDIM   5
#define NCOL   (DIMS * (NRELS + 1))   // 2176 weight cols: [self | rel0..rel15]
#define TCOL   (DIMS * NRELS)         // 2048 cols in T
#define NTILES (NCOL / 128)           // 17
#define TILE_HALVES (128 * 128)       // 16384 fp16 per B tile (fragment-major, 32 KB)

// -------------------- scratch ------------------------------------------------
__device__ float  g_hA[(size_t)MPAD * DIMS];
__device__ float  g_hB[(size_t)MPAD * DIMS];
__device__ __half g_T[(size_t)MPAD * TCOL];
// fragment-major fp16 weights: [layer][tile(17)][cj(16)][kp2(4)][lane(32)][w(4)][e(2)]
__device__ __half g_Bpack[NLAYER][(size_t)NCOL * DIMS];
__device__ int    g_cnt[NNODES * NRELS];

// -------------------- helpers ------------------------------------------------
__device__ __forceinline__ uint32_t smem_u32(const void* p) {
    uint32_t a;
    asm("{ .reg .u64 t; cvta.to.shared.u64 t, %1; cvt.u32.u64 %0, t; }" : "=r"(a) : "l"(p));
    return a;
}
__device__ __forceinline__ void red_add_v4(float* addr, float x, float y, float z, float w) {
    asm volatile("red.global.add.v4.f32 [%0], {%1, %2, %3, %4};"
                 :: "l"(addr), "f"(x), "f"(y), "f"(z), "f"(w) : "memory");
}
__device__ __forceinline__ void cp_async16(uint32_t saddr, const void* g) {
    asm volatile("cp.async.ca.shared.global [%0], [%1], 16;" :: "r"(saddr), "l"(g));
}
#define CP_COMMIT() asm volatile("cp.async.commit_group;")
#define CP_WAIT0()  asm volatile("cp.async.wait_group 0;")
#define CP_WAIT1()  asm volatile("cp.async.wait_group 1;")

__device__ __forceinline__ uint32_t pack_h2(float a, float b) {
    __half2 h = __floats2half2_rn(a, b);
    return *reinterpret_cast<uint32_t*>(&h);
}
__device__ __forceinline__ void mma_f16(float c[4], uint4 a, uint32_t b0, uint32_t b1) {
    asm volatile(
        "mma.sync.aligned.m16n8k16.row.col.f32.f16.f16.f32 "
        "{%0,%1,%2,%3}, {%4,%5,%6,%7}, {%8,%9}, {%0,%1,%2,%3};"
        : "+f"(c[0]), "+f"(c[1]), "+f"(c[2]), "+f"(c[3])
        : "r"(a.x), "r"(a.y), "r"(a.z), "r"(a.w), "r"(b0), "r"(b1));
}

// -------------------- small kernels -----------------------------------------
// pack weights into fragment-major fp16 (m16n8k16 B layout, two kp per uint4)
__global__ void pack_weights_kernel(const float* __restrict__ Wself,
                                    const float* __restrict__ Wrel) {
    int idx = blockIdx.x * blockDim.x + threadIdx.x;
    const int per_layer = NCOL * DIMS;          // 278528 halves
    const int total = NLAYER * per_layer;
    if (idx >= total) return;
    int l  = idx / per_layer;
    int hf = idx - l * per_layer;
    int e    = hf & 1;
    int w    = (hf >> 1) & 3;
    int lane = (hf >> 3) & 31;
    int kp2  = (hf >> 8) & 3;
    int cj   = (hf >> 10) & 15;
    int t    = hf >> 14;
    int qid = lane >> 2, rid = lane & 3;
    int kp   = kp2 * 2 + (w >> 1);
    int pair = w & 1;                       // 0: b0b1 (k in [0,8)), 1: b2b3 (k in [8,16))
    int k = kp * 16 + pair * 8 + rid * 2 + e;
    int n = t * 128 + cj * 8 + qid;
    float v;
    if (n < DIMS) {
        v = Wself[(l * DIMS + k) * DIMS + n];
    } else {
        int r = (n - DIMS) >> 7;
        int ee = (n - DIMS) & 127;
        v = Wrel[(((size_t)(l * NRELS + r) * DIMS) + k) * DIMS + ee];
    }
    g_Bpack[l][hf] = __float2half_rn(v);
}

__global__ void zero_cnt_kernel() {
    int i = blockIdx.x * blockDim.x + threadIdx.x;
    if (i < NNODES * NRELS) g_cnt[i] = 0;
}

__global__ void count_kernel(const int* __restrict__ dst, const int* __restrict__ et) {
    int e = blockIdx.x * blockDim.x + threadIdx.x;
    if (e >= NEDGE) return;
    atomicAdd(&g_cnt[dst[e] * NRELS + et[e]], 1);
}

__global__ void edge_agg_kernel(const int* __restrict__ src,
                                const int* __restrict__ dst,
                                const int* __restrict__ et,
                                float* __restrict__ hn) {
    int warp = (blockIdx.x * blockDim.x + threadIdx.x) >> 5;
    int lane = threadIdx.x & 31;
    if (warp >= NEDGE) return;
    int s = src[warp];
    int d = dst[warp];
    int r = et[warp];
    int c = g_cnt[d * NRELS + r];
    float we = 1.0f / (float)c;
    const uint2* row = reinterpret_cast<const uint2*>(g_T + (size_t)s * TCOL + r * DIMS);
    uint2 u = row[lane];
    __half2 p0 = *reinterpret_cast<__half2*>(&u.x);
    __half2 p1 = *reinterpret_cast<__half2*>(&u.y);
    float2 f0 = __half22float2(p0);
    float2 f1 = __half22float2(p1);
    red_add_v4(hn + (size_t)d * DIMS + lane * 4,
               f0.x * we, f0.y * we, f1.x * we, f1.y * we);
}

// -------------------- fp16 fragment-major GEMM --------------------------------
// 512 threads (16 warps, 4x4 over 128x128 tile). A staged fp32->permuted to
// fragment-major fp16 once; B arrives fragment-major via cp.async double buffer.
// All mainloop smem reads are LDS.128 conflict-free.
// smem bytes: A_frag [0, 32768) | Bs0 [32768, 65536) | Bs1 [65536, 98304)
// fp32 A scratch (64 KB) aliases Bs0+Bs1 during staging.
#define GEMM_SMEM 98304

__global__ void __launch_bounds__(512, 2)
gemm_kernel(const float* __restrict__ A,        // [MPAD,128] (layer 2)
            const int* __restrict__ nid,        // gather ids (layer 1) or null
            const float* __restrict__ emb,      // entity emb (layer 1)
            const __half* __restrict__ B,       // fragment-major fp16
            __half* __restrict__ T,
            float* __restrict__ hn,
            int relu_a) {
    extern __shared__ char smc[];
    uint4* AsF4 = reinterpret_cast<uint4*>(smc);              // 2048 uint4
    uint4* Bs0  = reinterpret_cast<uint4*>(smc + 32768);      // 2048 uint4
    uint4* Bs1  = reinterpret_cast<uint4*>(smc + 65536);
    float* scr  = reinterpret_cast<float*>(smc + 32768);      // 128x128 fp32
    const uint32_t sb = smem_u32(smc);

    const int tid = threadIdx.x;
    const int m0 = blockIdx.y * 128;
    const int t0 = (blockIdx.x == 0) ? 0 : 9;
    const int t1 = (blockIdx.x == 0) ? 9 : NTILES;

    // ---- stage 1: A tile row-major fp32 into scratch (coalesced)
    for (int i = tid; i < 128 * 32; i += 512) {
        int r = i >> 5, c4 = i & 31;
        const float* arow;
        if (nid) {
            int m = m0 + r;
            int id = nid[m < NNODES ? m : NNODES - 1];
            arow = emb + (size_t)id * DIMS;
        } else {
            arow = A + (size_t)(m0 + r) * DIMS;
        }
        float4 v = reinterpret_cast<const float4*>(arow)[c4];
        if (relu_a) {
            v.x = fmaxf(v.x, 0.f); v.y = fmaxf(v.y, 0.f);
            v.z = fmaxf(v.z, 0.f); v.w = fmaxf(v.w, 0.f);
        }
        *reinterpret_cast<float4*>(&scr[r * 128 + c4 * 4]) = v;
    }
    __syncthreads();

    // ---- stage 2: permute A to fragment-major fp16 (m16n8k16 A layout)
    // item = (bi*8 + kk)*32 + lane; uint4 = {a0a1, a2a3, a4a5, a6a7}
#pragma unroll
    for (int it = 0; it < 4; it++) {
        int item = tid + it * 512;
        int bi = item >> 8;
        int kk = (item >> 5) & 7;
        int ln = item & 31;
        int qid = ln >> 2, rid = ln & 3;
        int r0 = bi * 16 + qid;
        int c0 = kk * 16 + rid * 2;
        uint4 w;
        w.x = pack_h2(scr[r0 * 128 + c0],           scr[r0 * 128 + c0 + 1]);
        w.y = pack_h2(scr[(r0 + 8) * 128 + c0],     scr[(r0 + 8) * 128 + c0 + 1]);
        w.z = pack_h2(scr[r0 * 128 + c0 + 8],       scr[r0 * 128 + c0 + 9]);
        w.w = pack_h2(scr[(r0 + 8) * 128 + c0 + 8], scr[(r0 + 8) * 128 + c0 + 9]);
        AsF4[item] = w;
    }
    __syncthreads();    // all scr reads done before B prefetch clobbers it

    // ---- prefetch first B tile into Bs0 (32 KB contiguous)
    {
        const __half* Bt = B + (size_t)t0 * TILE_HALVES;
        uint32_t sbase = sb + 32768u;
        for (int i = tid; i < 2048; i += 512)
            cp_async16(sbase + (uint32_t)i * 16u, Bt + i * 8);
        CP_COMMIT();
    }

    const int wid  = tid >> 5;
    const int wm   = wid & 3;          // 4 warp rows (32 M each)
    const int wn   = wid >> 2;         // 4 warp cols (32 N each)
    const int lane = tid & 31;
    const int qid  = lane >> 2;
    const int rid  = lane & 3;

    for (int t = t0; t < t1; ++t) {
        uint4* Bs    = ((t - t0) & 1) ? Bs1 : Bs0;
        uint4* Bnext = ((t - t0) & 1) ? Bs0 : Bs1;

        if (t + 1 < t1) {
            const __half* Bt = B + (size_t)(t + 1) * TILE_HALVES;
            uint32_t sbase = sb + (uint32_t)((char*)Bnext - smc);
            for (int i = tid; i < 2048; i += 512)
                cp_async16(sbase + (uint32_t)i * 16u, Bt + i * 8);
            CP_COMMIT();
            CP_WAIT1();
        } else {
            CP_WAIT0();
        }
        __syncthreads();

        float c[2][4][4];
#pragma unroll
        for (int im = 0; im < 2; im++)
#pragma unroll
            for (int jn = 0; jn < 4; jn++)
#pragma unroll
                for (int q = 0; q < 4; q++) c[im][jn][q] = 0.f;

#pragma unroll
        for (int kp2 = 0; kp2 < 4; kp2++) {
            uint4 bf[4];
#pragma unroll
            for (int jn = 0; jn < 4; jn++)
                bf[jn] = Bs[(((wn * 4 + jn) * 4 + kp2) << 5) + lane];
#pragma unroll
            for (int sub = 0; sub < 2; sub++) {
                int kk = kp2 * 2 + sub;
                uint4 af[2];
                af[0] = AsF4[(((wm * 2 + 0) * 8 + kk) << 5) + lane];
                af[1] = AsF4[(((wm * 2 + 1) * 8 + kk) << 5) + lane];
#pragma unroll
                for (int im = 0; im < 2; im++)
#pragma unroll
                    for (int jn = 0; jn < 4; jn++) {
                        uint32_t b0 = sub ? bf[jn].z : bf[jn].x;
                        uint32_t b1 = sub ? bf[jn].w : bf[jn].y;
                        mma_f16(c[im][jn], af[im], b0, b1);
                    }
            }
        }

        // ---- in-register epilogue
        if (t == 0) {
#pragma unroll
            for (int im = 0; im < 2; im++) {
                int row = m0 + wm * 32 + im * 16 + qid;
#pragma unroll
                for (int jn = 0; jn < 4; jn++) {
                    int col = wn * 32 + jn * 8 + 2 * rid;
                    *reinterpret_cast<float2*>(hn + (size_t)row * DIMS + col)
                        = make_float2(c[im][jn][0], c[im][jn][1]);
                    *reinterpret_cast<float2*>(hn + (size_t)(row + 8) * DIMS + col)
                        = make_float2(c[im][jn][2], c[im][jn][3]);
                }
            }
        } else {
            int cbase = (t - 1) * 128 + wn * 32;
#pragma unroll
            for (int im = 0; im < 2; im++) {
                int row = m0 + wm * 32 + im * 16 + qid;
#pragma unroll
                for (int jn = 0; jn < 4; jn++) {
                    int col = cbase + jn * 8 + 2 * rid;
                    *reinterpret_cast<__half2*>(T + (size_t)row * TCOL + col)
                        = __floats2half2_rn(c[im][jn][0], c[im][jn][1]);
                    *reinterpret_cast<__half2*>(T + (size_t)(row + 8) * TCOL + col)
                        = __floats2half2_rn(c[im][jn][2], c[im][jn][3]);
                }
            }
        }
        __syncthreads();   // all warps done with Bs before refill
    }
}

// -------------------- scoring (relu fused) -----------------------------------
__global__ void score_kernel(const float* __restrict__ h,
                             const int* __restrict__ heads,
                             const int* __restrict__ rels,
                             const int* __restrict__ tails,
                             const float* __restrict__ rel_emb,
                             const float* __restrict__ path_feat,
                             const int* __restrict__ task_idx,
                             const float* __restrict__ delta_w,
                             const float* __restrict__ lambda_logit,
                             const float* __restrict__ rule_init,
                             float* __restrict__ out) {
    int warp = (blockIdx.x * blockDim.x + threadIdx.x) >> 5;
    int lane = threadIdx.x & 31;
    if (warp >= NQUERY) return;
    int hh = heads[warp], rr = rels[warp], tt = tails[warp];
    float4 a = reinterpret_cast<const float4*>(h + (size_t)hh * DIMS)[lane];
    float4 r = reinterpret_cast<const float4*>(rel_emb + (size_t)rr * DIMS)[lane];
    float4 b = reinterpret_cast<const float4*>(h + (size_t)tt * DIMS)[lane];
    a.x = fmaxf(a.x, 0.f); a.y = fmaxf(a.y, 0.f); a.z = fmaxf(a.z, 0.f); a.w = fmaxf(a.w, 0.f);
    b.x = fmaxf(b.x, 0.f); b.y = fmaxf(b.y, 0.f); b.z = fmaxf(b.z, 0.f); b.w = fmaxf(b.w, 0.f);
    float s = a.x * r.x * b.x + a.y * r.y * b.y + a.z * r.z * b.z + a.w * r.w * b.w;
#pragma unroll
    for (int off = 16; off > 0; off >>= 1)
        s += __shfl_xor_sync(0xFFFFFFFFu, s, off);
    if (lane == 0) {
        int idx = task_idx[0];
        float sp = 0.f;
#pragma unroll
        for (int p = 0; p < PDIM; p++)
            sp += path_feat[warp * PDIM + p] * (rule_init[idx * PDIM + p] + delta_w[idx * PDIM + p]);
        float lam = 1.0f / (1.0f + __expf(-lambda_logit[idx]));
        out[warp] = lam * s + (1.0f - lam) * sp;
    }
}

// -------------------- launcher -----------------------------------------------
extern "C" void kernel_launch(void* const* d_in, const int* in_sizes, int n_in,
                              void* d_out, int out_size) {
    const int*   node_ids   = (const int*)d_in[0];
    const int*   edge_index = (const int*)d_in[1];
    const int*   edge_type  = (const int*)d_in[2];
    const int*   heads      = (const int*)d_in[3];
    const int*   rels       = (const int*)d_in[4];
    const int*   tails      = (const int*)d_in[5];
    const float* path_feat  = (const float*)d_in[6];
    const int*   task_idx   = (const int*)d_in[7];
    const float* entity_emb = (const float*)d_in[8];
    const float* rel_emb    = (const float*)d_in[9];
    const float* W_self     = (const float*)d_in[10];
    const float* W_rel      = (const float*)d_in[11];
    const float* delta_w    = (const float*)d_in[12];
    const float* lambda_lg  = (const float*)d_in[13];
    const float* rule_init  = (const float*)d_in[14];
    float*       out        = (float*)d_out;

    const int* src = edge_index;
    const int* dst = edge_index + NEDGE;

    float *hA, *hB;
    __half *T, *Bpack;
    cudaGetSymbolAddress((void**)&hA, g_hA);
    cudaGetSymbolAddress((void**)&hB, g_hB);
    cudaGetSymbolAddress((void**)&T, g_T);
    cudaGetSymbolAddress((void**)&Bpack, g_Bpack);

    const int TPB = 256;
    cudaFuncSetAttribute(gemm_kernel,
                         cudaFuncAttributeMaxDynamicSharedMemorySize, GEMM_SMEM);

    pack_weights_kernel<<<(NLAYER * NCOL * DIMS + TPB - 1) / TPB, TPB>>>(W_self, W_rel);
    zero_cnt_kernel<<<(NNODES * NRELS + TPB - 1) / TPB, TPB>>>();
    count_kernel<<<(NEDGE + TPB - 1) / TPB, TPB>>>(dst, edge_type);

    dim3 grid(2, MPAD / 128);
    // layer 1: gather A from entity_emb via node_ids
    gemm_kernel<<<grid, 512, GEMM_SMEM>>>(nullptr, node_ids, entity_emb,
                                          Bpack, T, hB, 0);
    edge_agg_kernel<<<(NEDGE * 32 + TPB - 1) / TPB, TPB>>>(src, dst, edge_type, hB);
    // layer 2: A = relu(hB)
    gemm_kernel<<<grid, 512, GEMM_SMEM>>>(hB, nullptr, nullptr,
                                          Bpack + (size_t)NCOL * DIMS, T, hA, 1);
    edge_agg_kernel<<<(NEDGE * 32 + TPB - 1) / TPB, TPB>>>(src, dst, edge_type, hA);

    score_kernel<<<(NQUERY * 32 + TPB - 1) / TPB, TPB>>>(
        hA, heads, rels, tails, rel_emb, path_feat, task_idx,
        delta_w, lambda_lg, rule_init, out);
}

// round 8
// speedup vs baseline: 3.7950x; 1.0112x over previous
#include <cuda_runtime.h>
#include <cuda_fp16.h>
#include <cstdint>

#define NNODES 50000
#define MPAD   50048            // 391 * 128
#define NRELS  16
#define DIMS   128
#define NLAYER 2
#define NEDGE  600000
#define NQUERY 8192
#define PDIM   5
#define NCOL   (DIMS * (NRELS + 1))   // 2176 weight cols: [self | rel0..rel15]
#define TCOL   (DIMS * NRELS)         // 2048 cols in T
#define NTILES (NCOL / 128)           // 17
#define NPAIRS 9                      // ceil(17/2) pair-iterations
#define TILE_HALVES (128 * 128)       // 16384 fp16 per tile (fragment-major, 32 KB)

// -------------------- scratch ------------------------------------------------
__device__ float  g_hA[(size_t)MPAD * DIMS];
__device__ float  g_hB[(size_t)MPAD * DIMS];
__device__ __half g_T[(size_t)MPAD * TCOL];
// fragment-major fp16 weights: [layer][tile(17)][cj(16)][kp2(4)][lane(32)][w(4)][e(2)]
__device__ __half g_Bpack[NLAYER][(size_t)NCOL * DIMS];
__device__ int    g_cnt[NNODES * NRELS];

// -------------------- helpers ------------------------------------------------
__device__ __forceinline__ uint32_t smem_u32(const void* p) {
    uint32_t a;
    asm("{ .reg .u64 t; cvta.to.shared.u64 t, %1; cvt.u32.u64 %0, t; }" : "=r"(a) : "l"(p));
    return a;
}
__device__ __forceinline__ void red_add_v4(float* addr, float x, float y, float z, float w) {
    asm volatile("red.global.add.v4.f32 [%0], {%1, %2, %3, %4};"
                 :: "l"(addr), "f"(x), "f"(y), "f"(z), "f"(w) : "memory");
}
__device__ __forceinline__ void cp_async16(uint32_t saddr, const void* g) {
    asm volatile("cp.async.ca.shared.global [%0], [%1], 16;" :: "r"(saddr), "l"(g));
}
#define CP_COMMIT() asm volatile("cp.async.commit_group;")
#define CP_WAIT0()  asm volatile("cp.async.wait_group 0;")
#define CP_WAIT1()  asm volatile("cp.async.wait_group 1;")

__device__ __forceinline__ uint32_t pack_h2(float a, float b) {
    __half2 h = __floats2half2_rn(a, b);
    return *reinterpret_cast<uint32_t*>(&h);
}
__device__ __forceinline__ void mma_f16(float c[4], uint4 a, uint32_t b0, uint32_t b1) {
    asm volatile(
        "mma.sync.aligned.m16n8k16.row.col.f32.f16.f16.f32 "
        "{%0,%1,%2,%3}, {%4,%5,%6,%7}, {%8,%9}, {%0,%1,%2,%3};"
        : "+f"(c[0]), "+f"(c[1]), "+f"(c[2]), "+f"(c[3])
        : "r"(a.x), "r"(a.y), "r"(a.z), "r"(a.w), "r"(b0), "r"(b1));
}

// -------------------- small kernels -----------------------------------------
// pack weights into fragment-major fp16 (m16n8k16 B layout, two kp per uint4)
__global__ void pack_weights_kernel(const float* __restrict__ Wself,
                                    const float* __restrict__ Wrel) {
    int idx = blockIdx.x * blockDim.x + threadIdx.x;
    const int per_layer = NCOL * DIMS;          // 278528 halves
    const int total = NLAYER * per_layer;
    if (idx >= total) return;
    int l  = idx / per_layer;
    int hf = idx - l * per_layer;
    int e    = hf & 1;
    int w    = (hf >> 1) & 3;
    int lane = (hf >> 3) & 31;
    int kp2  = (hf >> 8) & 3;
    int cj   = (hf >> 10) & 15;
    int t    = hf >> 14;
    int qid = lane >> 2, rid = lane & 3;
    int kp   = kp2 * 2 + (w >> 1);
    int pair = w & 1;
    int k = kp * 16 + pair * 8 + rid * 2 + e;
    int n = t * 128 + cj * 8 + qid;
    float v;
    if (n < DIMS) {
        v = Wself[(l * DIMS + k) * DIMS + n];
    } else {
        int r = (n - DIMS) >> 7;
        int ee = (n - DIMS) & 127;
        v = Wrel[(((size_t)(l * NRELS + r) * DIMS) + k) * DIMS + ee];
    }
    g_Bpack[l][hf] = __float2half_rn(v);
}

__global__ void zero_cnt_kernel() {
    int i = blockIdx.x * blockDim.x + threadIdx.x;
    if (i < NNODES * NRELS) g_cnt[i] = 0;
}

__global__ void count_kernel(const int* __restrict__ dst, const int* __restrict__ et) {
    int e = blockIdx.x * blockDim.x + threadIdx.x;
    if (e >= NEDGE) return;
    atomicAdd(&g_cnt[dst[e] * NRELS + et[e]], 1);
}

__global__ void edge_agg_kernel(const int* __restrict__ src,
                                const int* __restrict__ dst,
                                const int* __restrict__ et,
                                float* __restrict__ hn) {
    int warp = (blockIdx.x * blockDim.x + threadIdx.x) >> 5;
    int lane = threadIdx.x & 31;
    if (warp >= NEDGE) return;
    int s = src[warp];
    int d = dst[warp];
    int r = et[warp];
    int c = g_cnt[d * NRELS + r];
    float we = 1.0f / (float)c;
    const uint2* row = reinterpret_cast<const uint2*>(g_T + (size_t)s * TCOL + r * DIMS);
    uint2 u = row[lane];
    __half2 p0 = *reinterpret_cast<__half2*>(&u.x);
    __half2 p1 = *reinterpret_cast<__half2*>(&u.y);
    float2 f0 = __half22float2(p0);
    float2 f1 = __half22float2(p1);
    red_add_v4(hn + (size_t)d * DIMS + lane * 4,
               f0.x * we, f0.y * we, f1.x * we, f1.y * we);
}

// -------------------- fp16 GEMM, 2-N-tile pairs, warp tile 32x64 --------------
// 512 threads (16 warps, 4 wm x 4 wn over 128x256 per iteration).
// A fragment-major fp16 staged once (32 KB); B pair double-buffered (2x64 KB).
// smem: A_frag [0,32K) | Bs0 [32K,96K) | Bs1 [96K,160K). A fp32 scratch aliases Bs0.
#define GEMM_SMEM 163840

__global__ void __launch_bounds__(512, 1)
gemm_kernel(const float* __restrict__ A,        // [MPAD,128] (layer 2)
            const int* __restrict__ nid,        // gather ids (layer 1) or null
            const float* __restrict__ emb,      // entity emb (layer 1)
            const __half* __restrict__ B,       // fragment-major fp16, 17 tiles
            __half* __restrict__ T,
            float* __restrict__ hn,
            int relu_a) {
    extern __shared__ char smc[];
    uint4* AsF4 = reinterpret_cast<uint4*>(smc);              // 2048 uint4
    uint4* Bs0  = reinterpret_cast<uint4*>(smc + 32768);      // 4096 uint4
    uint4* Bs1  = reinterpret_cast<uint4*>(smc + 98304);
    float* scr  = reinterpret_cast<float*>(smc + 32768);      // 128x128 fp32
    const uint32_t sb = smem_u32(smc);

    const int tid = threadIdx.x;
    const int m0 = blockIdx.x * 128;

    // ---- stage 1: A tile row-major fp32 into scratch (coalesced)
    for (int i = tid; i < 128 * 32; i += 512) {
        int r = i >> 5, c4 = i & 31;
        const float* arow;
        if (nid) {
            int m = m0 + r;
            int id = nid[m < NNODES ? m : NNODES - 1];
            arow = emb + (size_t)id * DIMS;
        } else {
            arow = A + (size_t)(m0 + r) * DIMS;
        }
        float4 v = reinterpret_cast<const float4*>(arow)[c4];
        if (relu_a) {
            v.x = fmaxf(v.x, 0.f); v.y = fmaxf(v.y, 0.f);
            v.z = fmaxf(v.z, 0.f); v.w = fmaxf(v.w, 0.f);
        }
        *reinterpret_cast<float4*>(&scr[r * 128 + c4 * 4]) = v;
    }
    __syncthreads();

    // ---- stage 2: permute A to fragment-major fp16 (m16n8k16 A layout)
#pragma unroll
    for (int it = 0; it < 4; it++) {
        int item = tid + it * 512;
        int bi = item >> 8;
        int kk = (item >> 5) & 7;
        int ln = item & 31;
        int q = ln >> 2, rd = ln & 3;
        int r0 = bi * 16 + q;
        int c0 = kk * 16 + rd * 2;
        uint4 w;
        w.x = pack_h2(scr[r0 * 128 + c0],           scr[r0 * 128 + c0 + 1]);
        w.y = pack_h2(scr[(r0 + 8) * 128 + c0],     scr[(r0 + 8) * 128 + c0 + 1]);
        w.z = pack_h2(scr[r0 * 128 + c0 + 8],       scr[r0 * 128 + c0 + 9]);
        w.w = pack_h2(scr[(r0 + 8) * 128 + c0 + 8], scr[(r0 + 8) * 128 + c0 + 9]);
        AsF4[item] = w;
    }
    __syncthreads();    // all scr reads done before B prefetch clobbers it

    // ---- prefetch pair 0 (tiles 0,1) into Bs0
    {
        const __half* Bt = B;
        uint32_t sbase = sb + 32768u;
        for (int i = tid; i < 4096; i += 512)
            cp_async16(sbase + (uint32_t)i * 16u, Bt + i * 8);
        CP_COMMIT();
    }

    const int wid  = tid >> 5;
    const int wm   = wid & 3;          // 4 warp rows (32 M each)
    const int wn   = wid >> 2;         // 4 warp cols (64 N each, spanning 2 tiles)
    const int lane = tid & 31;
    const int qid  = lane >> 2;
    const int rid  = lane & 3;

    for (int it = 0; it < NPAIRS; ++it) {
        uint4* Bs    = (it & 1) ? Bs1 : Bs0;
        uint4* Bnext = (it & 1) ? Bs0 : Bs1;

        if (it + 1 < NPAIRS) {
            int cnt = (it + 1 == NPAIRS - 1) ? 2048 : 4096;   // last pair = 1 tile
            const __half* Bt = B + (size_t)(it + 1) * 2 * TILE_HALVES;
            uint32_t sbase = sb + (uint32_t)((char*)Bnext - smc);
            for (int i = tid; i < cnt; i += 512)
                cp_async16(sbase + (uint32_t)i * 16u, Bt + i * 8);
            CP_COMMIT();
            CP_WAIT1();
        } else {
            CP_WAIT0();
        }
        __syncthreads();

        const int gc0 = it * 256 + wn * 64;   // warp's first global col
        if (gc0 < NCOL) {
            float c[2][8][4];
#pragma unroll
            for (int im = 0; im < 2; im++)
#pragma unroll
                for (int jn = 0; jn < 8; jn++)
#pragma unroll
                    for (int q = 0; q < 4; q++) c[im][jn][q] = 0.f;

#pragma unroll
            for (int kp2 = 0; kp2 < 4; kp2++) {
                uint4 bf[8];
#pragma unroll
                for (int jn = 0; jn < 8; jn++)
                    bf[jn] = Bs[(((wn * 8 + jn) * 4 + kp2) << 5) + lane];
#pragma unroll
                for (int sub = 0; sub < 2; sub++) {
                    int kk = kp2 * 2 + sub;
                    uint4 af[2];
                    af[0] = AsF4[(((wm * 2 + 0) * 8 + kk) << 5) + lane];
                    af[1] = AsF4[(((wm * 2 + 1) * 8 + kk) << 5) + lane];
#pragma unroll
                    for (int im = 0; im < 2; im++)
#pragma unroll
                        for (int jn = 0; jn < 8; jn++) {
                            uint32_t b0 = sub ? bf[jn].z : bf[jn].x;
                            uint32_t b1 = sub ? bf[jn].w : bf[jn].y;
                            mma_f16(c[im][jn], af[im], b0, b1);
                        }
                }
            }

            // ---- in-register epilogue (warp-uniform destination)
            if (gc0 < DIMS) {     // self block -> hn (fp32)
#pragma unroll
                for (int im = 0; im < 2; im++) {
                    int row = m0 + wm * 32 + im * 16 + qid;
#pragma unroll
                    for (int jn = 0; jn < 8; jn++) {
                        int col = gc0 + jn * 8 + 2 * rid;
                        *reinterpret_cast<float2*>(hn + (size_t)row * DIMS + col)
                            = make_float2(c[im][jn][0], c[im][jn][1]);
                        *reinterpret_cast<float2*>(hn + (size_t)(row + 8) * DIMS + col)
                            = make_float2(c[im][jn][2], c[im][jn][3]);
                    }
                }
            } else {              // relation blocks -> T (fp16)
                int cb = gc0 - DIMS;
#pragma unroll
                for (int im = 0; im < 2; im++) {
                    int row = m0 + wm * 32 + im * 16 + qid;
#pragma unroll
                    for (int jn = 0; jn < 8; jn++) {
                        int col = cb + jn * 8 + 2 * rid;
                        *reinterpret_cast<__half2*>(T + (size_t)row * TCOL + col)
                            = __floats2half2_rn(c[im][jn][0], c[im][jn][1]);
                        *reinterpret_cast<__half2*>(T + (size_t)(row + 8) * TCOL + col)
                            = __floats2half2_rn(c[im][jn][2], c[im][jn][3]);
                    }
                }
            }
        }
        __syncthreads();   // all warps done with Bs before refill
    }
}

// -------------------- scoring (relu fused) -----------------------------------
__global__ void score_kernel(const float* __restrict__ h,
                             const int* __restrict__ heads,
                             const int* __restrict__ rels,
                             const int* __restrict__ tails,
                             const float* __restrict__ rel_emb,
                             const float* __restrict__ path_feat,
                             const int* __restrict__ task_idx,
                             const float* __restrict__ delta_w,
                             const float* __restrict__ lambda_logit,
                             const float* __restrict__ rule_init,
                             float* __restrict__ out) {
    int warp = (blockIdx.x * blockDim.x + threadIdx.x) >> 5;
    int lane = threadIdx.x & 31;
    if (warp >= NQUERY) return;
    int hh = heads[warp], rr = rels[warp], tt = tails[warp];
    float4 a = reinterpret_cast<const float4*>(h + (size_t)hh * DIMS)[lane];
    float4 r = reinterpret_cast<const float4*>(rel_emb + (size_t)rr * DIMS)[lane];
    float4 b = reinterpret_cast<const float4*>(h + (size_t)tt * DIMS)[lane];
    a.x = fmaxf(a.x, 0.f); a.y = fmaxf(a.y, 0.f); a.z = fmaxf(a.z, 0.f); a.w = fmaxf(a.w, 0.f);
    b.x = fmaxf(b.x, 0.f); b.y = fmaxf(b.y, 0.f); b.z = fmaxf(b.z, 0.f); b.w = fmaxf(b.w, 0.f);
    float s = a.x * r.x * b.x + a.y * r.y * b.y + a.z * r.z * b.z + a.w * r.w * b.w;
#pragma unroll
    for (int off = 16; off > 0; off >>= 1)
        s += __shfl_xor_sync(0xFFFFFFFFu, s, off);
    if (lane == 0) {
        int idx = task_idx[0];
        float sp = 0.f;
#pragma unroll
        for (int p = 0; p < PDIM; p++)
            sp += path_feat[warp * PDIM + p] * (rule_init[idx * PDIM + p] + delta_w[idx * PDIM + p]);
        float lam = 1.0f / (1.0f + __expf(-lambda_logit[idx]));
        out[warp] = lam * s + (1.0f - lam) * sp;
    }
}

// -------------------- launcher -----------------------------------------------
extern "C" void kernel_launch(void* const* d_in, const int* in_sizes, int n_in,
                              void* d_out, int out_size) {
    const int*   node_ids   = (const int*)d_in[0];
    const int*   edge_index = (const int*)d_in[1];
    const int*   edge_type  = (const int*)d_in[2];
    const int*   heads      = (const int*)d_in[3];
    const int*   rels       = (const int*)d_in[4];
    const int*   tails      = (const int*)d_in[5];
    const float* path_feat  = (const float*)d_in[6];
    const int*   task_idx   = (const int*)d_in[7];
    const float* entity_emb = (const float*)d_in[8];
    const float* rel_emb    = (const float*)d_in[9];
    const float* W_self     = (const float*)d_in[10];
    const float* W_rel      = (const float*)d_in[11];
    const float* delta_w    = (const float*)d_in[12];
    const float* lambda_lg  = (const float*)d_in[13];
    const float* rule_init  = (const float*)d_in[14];
    float*       out        = (float*)d_out;

    const int* src = edge_index;
    const int* dst = edge_index + NEDGE;

    float *hA, *hB;
    __half *T, *Bpack;
    cudaGetSymbolAddress((void**)&hA, g_hA);
    cudaGetSymbolAddress((void**)&hB, g_hB);
    cudaGetSymbolAddress((void**)&T, g_T);
    cudaGetSymbolAddress((void**)&Bpack, g_Bpack);

    const int TPB = 256;
    cudaFuncSetAttribute(gemm_kernel,
                         cudaFuncAttributeMaxDynamicSharedMemorySize, GEMM_SMEM);

    pack_weights_kernel<<<(NLAYER * NCOL * DIMS + TPB - 1) / TPB, TPB>>>(W_self, W_rel);
    zero_cnt_kernel<<<(NNODES * NRELS + TPB - 1) / TPB, TPB>>>();
    count_kernel<<<(NEDGE + TPB - 1) / TPB, TPB>>>(dst, edge_type);

    // layer 1: gather A from entity_emb via node_ids
    gemm_kernel<<<MPAD / 128, 512, GEMM_SMEM>>>(nullptr, node_ids, entity_emb,
                                                Bpack, T, hB, 0);
    edge_agg_kernel<<<(NEDGE * 32 + TPB - 1) / TPB, TPB>>>(src, dst, edge_type, hB);
    // layer 2: A = relu(hB)
    gemm_kernel<<<MPAD / 128, 512, GEMM_SMEM>>>(hB, nullptr, nullptr,
                                                Bpack + (size_t)NCOL * DIMS, T, hA, 1);
    edge_agg_kernel<<<(NEDGE * 32 + TPB - 1) / TPB, TPB>>>(src, dst, edge_type, hA);

    score_kernel<<<(NQUERY * 32 + TPB - 1) / TPB, TPB>>>(
        hA, heads, rels, tails, rel_emb, path_feat, task_idx,
        delta_w, lambda_lg, rule_init, out);
}

// round 9
// speedup vs baseline: 3.9445x; 1.0394x over previous
#include <cuda_runtime.h>
#include <cuda_fp16.h>
#include <cstdint>

#define NNODES 50000
#define MPAD   50048            // 391 * 128
#define NRELS  16
#define DIMS   128
#define NLAYER 2
#define NEDGE  600000
#define NQUERY 8192
#define PDIM   5
#define NCOL   (DIMS * (NRELS + 1))   // 2176 weight cols: [self | rel0..rel15]
#define TCOL   (DIMS * NRELS)         // 2048 cols in T
#define NTILES (NCOL / 128)           // 17
#define NPAIRS 9                      // ceil(17/2)
#define TILE_HALVES (128 * 128)       // fp16 per tile (fragment-major, 32 KB)

// -------------------- scratch ------------------------------------------------
__device__ float  g_hA[(size_t)MPAD * DIMS];
__device__ float  g_hB[(size_t)MPAD * DIMS];
__device__ __half g_T[(size_t)MPAD * TCOL];
__device__ __half g_Bpack[NLAYER][(size_t)NCOL * DIMS];
__device__ int    g_cnt[NNODES * NRELS];
// counting sort of edges by dst
__device__ int      g_off[NNODES + 1];
__device__ int      g_cur[NNODES];
__device__ uint32_t g_epack[NEDGE];   // src | (rel<<16)

// -------------------- helpers ------------------------------------------------
__device__ __forceinline__ uint32_t smem_u32(const void* p) {
    uint32_t a;
    asm("{ .reg .u64 t; cvta.to.shared.u64 t, %1; cvt.u32.u64 %0, t; }" : "=r"(a) : "l"(p));
    return a;
}
__device__ __forceinline__ void cp_async16(uint32_t saddr, const void* g) {
    asm volatile("cp.async.ca.shared.global [%0], [%1], 16;" :: "r"(saddr), "l"(g));
}
#define CP_COMMIT() asm volatile("cp.async.commit_group;")
#define CP_WAIT0()  asm volatile("cp.async.wait_group 0;")
#define CP_WAIT1()  asm volatile("cp.async.wait_group 1;")

__device__ __forceinline__ uint32_t pack_h2(float a, float b) {
    __half2 h = __floats2half2_rn(a, b);
    return *reinterpret_cast<uint32_t*>(&h);
}
__device__ __forceinline__ void mma_f16(float c[4], uint4 a, uint32_t b0, uint32_t b1) {
    asm volatile(
        "mma.sync.aligned.m16n8k16.row.col.f32.f16.f16.f32 "
        "{%0,%1,%2,%3}, {%4,%5,%6,%7}, {%8,%9}, {%0,%1,%2,%3};"
        : "+f"(c[0]), "+f"(c[1]), "+f"(c[2]), "+f"(c[3])
        : "r"(a.x), "r"(a.y), "r"(a.z), "r"(a.w), "r"(b0), "r"(b1));
}

// -------------------- weight packing (fragment-major fp16) -------------------
__global__ void pack_weights_kernel(const float* __restrict__ Wself,
                                    const float* __restrict__ Wrel) {
    int idx = blockIdx.x * blockDim.x + threadIdx.x;
    const int per_layer = NCOL * DIMS;
    const int total = NLAYER * per_layer;
    if (idx >= total) return;
    int l  = idx / per_layer;
    int hf = idx - l * per_layer;
    int e    = hf & 1;
    int w    = (hf >> 1) & 3;
    int lane = (hf >> 3) & 31;
    int kp2  = (hf >> 8) & 3;
    int cj   = (hf >> 10) & 15;
    int t    = hf >> 14;
    int qid = lane >> 2, rid = lane & 3;
    int kp   = kp2 * 2 + (w >> 1);
    int pair = w & 1;
    int k = kp * 16 + pair * 8 + rid * 2 + e;
    int n = t * 128 + cj * 8 + qid;
    float v;
    if (n < DIMS) {
        v = Wself[(l * DIMS + k) * DIMS + n];
    } else {
        int r = (n - DIMS) >> 7;
        int ee = (n - DIMS) & 127;
        v = Wrel[(((size_t)(l * NRELS + r) * DIMS) + k) * DIMS + ee];
    }
    g_Bpack[l][hf] = __float2half_rn(v);
}

// -------------------- edge prep: counts + counting sort by dst ---------------
__global__ void zero_prep_kernel() {
    int i = blockIdx.x * blockDim.x + threadIdx.x;
    if (i < NNODES * NRELS) g_cnt[i] = 0;
    if (i < NNODES + 1) g_off[i] = 0;
}

__global__ void hist_kernel(const int* __restrict__ dst, const int* __restrict__ et) {
    int e = blockIdx.x * blockDim.x + threadIdx.x;
    if (e >= NEDGE) return;
    int d = dst[e];
    atomicAdd(&g_cnt[d * NRELS + et[e]], 1);
    atomicAdd(&g_off[d + 1], 1);
}

// single-block inclusive scan of g_off[0..NNODES]; also init cursors
__global__ void scan_kernel() {
    __shared__ int part[1024];
    const int t = threadIdx.x;
    const int total = NNODES + 1;
    const int chunk = (total + 1023) / 1024;     // 49
    int lo = t * chunk;
    int hi = min(lo + chunk, total);
    int sum = 0;
    for (int i = lo; i < hi; i++) sum += g_off[i];
    part[t] = sum;
    __syncthreads();
#pragma unroll
    for (int off = 1; off < 1024; off <<= 1) {
        int v = (t >= off) ? part[t - off] : 0;
        __syncthreads();
        part[t] += v;
        __syncthreads();
    }
    int prefix = (t == 0) ? 0 : part[t - 1];
    for (int i = lo; i < hi; i++) {
        prefix += g_off[i];
        g_off[i] = prefix;                        // inclusive scan
        if (i < NNODES) g_cur[i] = prefix;        // bucket cursor = start of bucket i
    }
}

__global__ void scatter_kernel(const int* __restrict__ src,
                               const int* __restrict__ dst,
                               const int* __restrict__ et) {
    int e = blockIdx.x * blockDim.x + threadIdx.x;
    if (e >= NEDGE) return;
    int d = dst[e];
    int pos = atomicAdd(&g_cur[d], 1);
    g_epack[pos] = (uint32_t)src[e] | ((uint32_t)et[e] << 16);
}

// -------------------- grouped aggregation (no atomics) -----------------------
// one warp per dst: stream its edges' T rows, accumulate in regs, add to hn row
__global__ void __launch_bounds__(256)
group_agg_kernel(float* __restrict__ hn) {
    int warp = (blockIdx.x * blockDim.x + threadIdx.x) >> 5;
    int lane = threadIdx.x & 31;
    if (warp >= NNODES) return;
    int beg = g_off[warp];
    int end = g_off[warp + 1];
    if (beg == end) return;

    float4 acc = make_float4(0.f, 0.f, 0.f, 0.f);
    uint32_t p = g_epack[beg];
    for (int i = beg; i < end; i++) {
        uint32_t pn = (i + 1 < end) ? g_epack[i + 1] : 0u;   // prefetch next
        int s = p & 0xFFFF;
        int r = p >> 16;
        float w = 1.0f / (float)g_cnt[warp * NRELS + r];
        uint2 u = *reinterpret_cast<const uint2*>(
            g_T + (size_t)s * TCOL + r * DIMS + lane * 4);
        float2 f0 = __half22float2(*reinterpret_cast<__half2*>(&u.x));
        float2 f1 = __half22float2(*reinterpret_cast<__half2*>(&u.y));
        acc.x += w * f0.x; acc.y += w * f0.y;
        acc.z += w * f1.x; acc.w += w * f1.y;
        p = pn;
    }
    float* o = hn + (size_t)warp * DIMS + lane * 4;
    float4 cur = *reinterpret_cast<float4*>(o);
    cur.x += acc.x; cur.y += acc.y; cur.z += acc.z; cur.w += acc.w;
    *reinterpret_cast<float4*>(o) = cur;
}

// -------------------- fp16 GEMM (unchanged from R8) --------------------------
#define GEMM_SMEM 163840

__global__ void __launch_bounds__(512, 1)
gemm_kernel(const float* __restrict__ A,
            const int* __restrict__ nid,
            const float* __restrict__ emb,
            const __half* __restrict__ B,
            __half* __restrict__ T,
            float* __restrict__ hn,
            int relu_a) {
    extern __shared__ char smc[];
    uint4* AsF4 = reinterpret_cast<uint4*>(smc);
    uint4* Bs0  = reinterpret_cast<uint4*>(smc + 32768);
    uint4* Bs1  = reinterpret_cast<uint4*>(smc + 98304);
    float* scr  = reinterpret_cast<float*>(smc + 32768);
    const uint32_t sb = smem_u32(smc);

    const int tid = threadIdx.x;
    const int m0 = blockIdx.x * 128;

    for (int i = tid; i < 128 * 32; i += 512) {
        int r = i >> 5, c4 = i & 31;
        const float* arow;
        if (nid) {
            int m = m0 + r;
            int id = nid[m < NNODES ? m : NNODES - 1];
            arow = emb + (size_t)id * DIMS;
        } else {
            arow = A + (size_t)(m0 + r) * DIMS;
        }
        float4 v = reinterpret_cast<const float4*>(arow)[c4];
        if (relu_a) {
            v.x = fmaxf(v.x, 0.f); v.y = fmaxf(v.y, 0.f);
            v.z = fmaxf(v.z, 0.f); v.w = fmaxf(v.w, 0.f);
        }
        *reinterpret_cast<float4*>(&scr[r * 128 + c4 * 4]) = v;
    }
    __syncthreads();

#pragma unroll
    for (int it = 0; it < 4; it++) {
        int item = tid + it * 512;
        int bi = item >> 8;
        int kk = (item >> 5) & 7;
        int ln = item & 31;
        int q = ln >> 2, rd = ln & 3;
        int r0 = bi * 16 + q;
        int c0 = kk * 16 + rd * 2;
        uint4 w;
        w.x = pack_h2(scr[r0 * 128 + c0],           scr[r0 * 128 + c0 + 1]);
        w.y = pack_h2(scr[(r0 + 8) * 128 + c0],     scr[(r0 + 8) * 128 + c0 + 1]);
        w.z = pack_h2(scr[r0 * 128 + c0 + 8],       scr[r0 * 128 + c0 + 9]);
        w.w = pack_h2(scr[(r0 + 8) * 128 + c0 + 8], scr[(r0 + 8) * 128 + c0 + 9]);
        AsF4[item] = w;
    }
    __syncthreads();

    {
        const __half* Bt = B;
        uint32_t sbase = sb + 32768u;
        for (int i = tid; i < 4096; i += 512)
            cp_async16(sbase + (uint32_t)i * 16u, Bt + i * 8);
        CP_COMMIT();
    }

    const int wid  = tid >> 5;
    const int wm   = wid & 3;
    const int wn   = wid >> 2;
    const int lane = tid & 31;
    const int qid  = lane >> 2;
    const int rid  = lane & 3;

    for (int it = 0; it < NPAIRS; ++it) {
        uint4* Bs    = (it & 1) ? Bs1 : Bs0;
        uint4* Bnext = (it & 1) ? Bs0 : Bs1;

        if (it + 1 < NPAIRS) {
            int cnt = (it + 1 == NPAIRS - 1) ? 2048 : 4096;
            const __half* Bt = B + (size_t)(it + 1) * 2 * TILE_HALVES;
            uint32_t sbase = sb + (uint32_t)((char*)Bnext - smc);
            for (int i = tid; i < cnt; i += 512)
                cp_async16(sbase + (uint32_t)i * 16u, Bt + i * 8);
            CP_COMMIT();
            CP_WAIT1();
        } else {
            CP_WAIT0();
        }
        __syncthreads();

        const int gc0 = it * 256 + wn * 64;
        if (gc0 < NCOL) {
            float c[2][8][4];
#pragma unroll
            for (int im = 0; im < 2; im++)
#pragma unroll
                for (int jn = 0; jn < 8; jn++)
#pragma unroll
                    for (int q = 0; q < 4; q++) c[im][jn][q] = 0.f;

#pragma unroll
            for (int kp2 = 0; kp2 < 4; kp2++) {
                uint4 bf[8];
#pragma unroll
                for (int jn = 0; jn < 8; jn++)
                    bf[jn] = Bs[(((wn * 8 + jn) * 4 + kp2) << 5) + lane];
#pragma unroll
                for (int sub = 0; sub < 2; sub++) {
                    int kk = kp2 * 2 + sub;
                    uint4 af[2];
                    af[0] = AsF4[(((wm * 2 + 0) * 8 + kk) << 5) + lane];
                    af[1] = AsF4[(((wm * 2 + 1) * 8 + kk) << 5) + lane];
#pragma unroll
                    for (int im = 0; im < 2; im++)
#pragma unroll
                        for (int jn = 0; jn < 8; jn++) {
                            uint32_t b0 = sub ? bf[jn].z : bf[jn].x;
                            uint32_t b1 = sub ? bf[jn].w : bf[jn].y;
                            mma_f16(c[im][jn], af[im], b0, b1);
                        }
                }
            }

            if (gc0 < DIMS) {
#pragma unroll
                for (int im = 0; im < 2; im++) {
                    int row = m0 + wm * 32 + im * 16 + qid;
#pragma unroll
                    for (int jn = 0; jn < 8; jn++) {
                        int col = gc0 + jn * 8 + 2 * rid;
                        *reinterpret_cast<float2*>(hn + (size_t)row * DIMS + col)
                            = make_float2(c[im][jn][0], c[im][jn][1]);
                        *reinterpret_cast<float2*>(hn + (size_t)(row + 8) * DIMS + col)
                            = make_float2(c[im][jn][2], c[im][jn][3]);
                    }
                }
            } else {
                int cb = gc0 - DIMS;
#pragma unroll
                for (int im = 0; im < 2; im++) {
                    int row = m0 + wm * 32 + im * 16 + qid;
#pragma unroll
                    for (int jn = 0; jn < 8; jn++) {
                        int col = cb + jn * 8 + 2 * rid;
                        *reinterpret_cast<__half2*>(T + (size_t)row * TCOL + col)
                            = __floats2half2_rn(c[im][jn][0], c[im][jn][1]);
                        *reinterpret_cast<__half2*>(T + (size_t)(row + 8) * TCOL + col)
                            = __floats2half2_rn(c[im][jn][2], c[im][jn][3]);
                    }
                }
            }
        }
        __syncthreads();
    }
}

// -------------------- scoring (relu fused) -----------------------------------
__global__ void score_kernel(const float* __restrict__ h,
                             const int* __restrict__ heads,
                             const int* __restrict__ rels,
                             const int* __restrict__ tails,
                             const float* __restrict__ rel_emb,
                             const float* __restrict__ path_feat,
                             const int* __restrict__ task_idx,
                             const float* __restrict__ delta_w,
                             const float* __restrict__ lambda_logit,
                             const float* __restrict__ rule_init,
                             float* __restrict__ out) {
    int warp = (blockIdx.x * blockDim.x + threadIdx.x) >> 5;
    int lane = threadIdx.x & 31;
    if (warp >= NQUERY) return;
    int hh = heads[warp], rr = rels[warp], tt = tails[warp];
    float4 a = reinterpret_cast<const float4*>(h + (size_t)hh * DIMS)[lane];
    float4 r = reinterpret_cast<const float4*>(rel_emb + (size_t)rr * DIMS)[lane];
    float4 b = reinterpret_cast<const float4*>(h + (size_t)tt * DIMS)[lane];
    a.x = fmaxf(a.x, 0.f); a.y = fmaxf(a.y, 0.f); a.z = fmaxf(a.z, 0.f); a.w = fmaxf(a.w, 0.f);
    b.x = fmaxf(b.x, 0.f); b.y = fmaxf(b.y, 0.f); b.z = fmaxf(b.z, 0.f); b.w = fmaxf(b.w, 0.f);
    float s = a.x * r.x * b.x + a.y * r.y * b.y + a.z * r.z * b.z + a.w * r.w * b.w;
#pragma unroll
    for (int off = 16; off > 0; off >>= 1)
        s += __shfl_xor_sync(0xFFFFFFFFu, s, off);
    if (lane == 0) {
        int idx = task_idx[0];
        float sp = 0.f;
#pragma unroll
        for (int p = 0; p < PDIM; p++)
            sp += path_feat[warp * PDIM + p] * (rule_init[idx * PDIM + p] + delta_w[idx * PDIM + p]);
        float lam = 1.0f / (1.0f + __expf(-lambda_logit[idx]));
        out[warp] = lam * s + (1.0f - lam) * sp;
    }
}

// -------------------- launcher -----------------------------------------------
extern "C" void kernel_launch(void* const* d_in, const int* in_sizes, int n_in,
                              void* d_out, int out_size) {
    const int*   node_ids   = (const int*)d_in[0];
    const int*   edge_index = (const int*)d_in[1];
    const int*   edge_type  = (const int*)d_in[2];
    const int*   heads      = (const int*)d_in[3];
    const int*   rels       = (const int*)d_in[4];
    const int*   tails      = (const int*)d_in[5];
    const float* path_feat  = (const float*)d_in[6];
    const int*   task_idx   = (const int*)d_in[7];
    const float* entity_emb = (const float*)d_in[8];
    const float* rel_emb    = (const float*)d_in[9];
    const float* W_self     = (const float*)d_in[10];
    const float* W_rel      = (const float*)d_in[11];
    const float* delta_w    = (const float*)d_in[12];
    const float* lambda_lg  = (const float*)d_in[13];
    const float* rule_init  = (const float*)d_in[14];
    float*       out        = (float*)d_out;

    const int* src = edge_index;
    const int* dst = edge_index + NEDGE;

    float *hA, *hB;
    __half *T, *Bpack;
    cudaGetSymbolAddress((void**)&hA, g_hA);
    cudaGetSymbolAddress((void**)&hB, g_hB);
    cudaGetSymbolAddress((void**)&T, g_T);
    cudaGetSymbolAddress((void**)&Bpack, g_Bpack);

    const int TPB = 256;
    cudaFuncSetAttribute(gemm_kernel,
                         cudaFuncAttributeMaxDynamicSharedMemorySize, GEMM_SMEM);

    // prep: weights + edge counting-sort (once; reused by both layers)
    pack_weights_kernel<<<(NLAYER * NCOL * DIMS + TPB - 1) / TPB, TPB>>>(W_self, W_rel);
    zero_prep_kernel<<<(NNODES * NRELS + TPB - 1) / TPB, TPB>>>();
    hist_kernel<<<(NEDGE + TPB - 1) / TPB, TPB>>>(dst, edge_type);
    scan_kernel<<<1, 1024>>>();
    scatter_kernel<<<(NEDGE + TPB - 1) / TPB, TPB>>>(src, dst, edge_type);

    const int agg_blocks = (NNODES * 32 + TPB - 1) / TPB;
    // layer 1
    gemm_kernel<<<MPAD / 128, 512, GEMM_SMEM>>>(nullptr, node_ids, entity_emb,
                                                Bpack, T, hB, 0);
    group_agg_kernel<<<agg_blocks, TPB>>>(hB);
    // layer 2
    gemm_kernel<<<MPAD / 128, 512, GEMM_SMEM>>>(hB, nullptr, nullptr,
                                                Bpack + (size_t)NCOL * DIMS, T, hA, 1);
    group_agg_kernel<<<agg_blocks, TPB>>>(hA);

    score_kernel<<<(NQUERY * 32 + TPB - 1) / TPB, TPB>>>(
        hA, heads, rels, tails, rel_emb, path_feat, task_idx,
        delta_w, lambda_lg, rule_init, out);
}

// round 10
// speedup vs baseline: 5.2438x; 1.3294x over previous
#include <cuda_runtime.h>
#include <cuda_fp16.h>
#include <cstdint>

#define NNODES 50000
#define MPAD   50048            // 391 * 128
#define NRELS  16
#define DIMS   128
#define NLAYER 2
#define NEDGE  600000
#define NQUERY 8192
#define PDIM   5
#define NCOL   (DIMS * (NRELS + 1))   // 2176
#define TCOL   (DIMS * NRELS)         // 2048
#define NTILES 17
#define MTILES 391                    // 17 * 23
#define MGROUP 23                     // M tiles per block
#define TILE_HALVES (128 * 128)       // fp16 per B tile (32 KB)
#define SCANB  49                     // scan blocks (49*1024 >= 50001)

// -------------------- scratch ------------------------------------------------
__device__ float  g_hA[(size_t)MPAD * DIMS];
__device__ float  g_hB[(size_t)MPAD * DIMS];
__device__ __half g_T[(size_t)MPAD * TCOL];
__device__ __half g_Bpack[NLAYER][(size_t)NCOL * DIMS];   // fragment-major fp16
__device__ uint4  g_Afrag[(size_t)MTILES * 2048];         // fragment-major fp16 A
__device__ int    g_cnt[NNODES * NRELS];
__device__ int    g_deg[NNODES];
__device__ int    g_off[NNODES + 1];
__device__ int    g_cur[NNODES];
__device__ int    g_bt[SCANB + 1];
__device__ uint32_t g_epack[NEDGE];   // src | (rel<<16)

// -------------------- helpers ------------------------------------------------
__device__ __forceinline__ uint32_t smem_u32(const void* p) {
    uint32_t a;
    asm("{ .reg .u64 t; cvta.to.shared.u64 t, %1; cvt.u32.u64 %0, t; }" : "=r"(a) : "l"(p));
    return a;
}
__device__ __forceinline__ void cp_async16(uint32_t saddr, const void* g) {
    asm volatile("cp.async.ca.shared.global [%0], [%1], 16;" :: "r"(saddr), "l"(g));
}
#define CP_COMMIT() asm volatile("cp.async.commit_group;")
#define CP_WAIT0()  asm volatile("cp.async.wait_group 0;")
#define CP_WAIT1()  asm volatile("cp.async.wait_group 1;")

__device__ __forceinline__ uint32_t pack_h2(float a, float b) {
    __half2 h = __floats2half2_rn(a, b);
    return *reinterpret_cast<uint32_t*>(&h);
}
__device__ __forceinline__ void mma_f16(float c[4], uint4 a, uint32_t b0, uint32_t b1) {
    asm volatile(
        "mma.sync.aligned.m16n8k16.row.col.f32.f16.f16.f32 "
        "{%0,%1,%2,%3}, {%4,%5,%6,%7}, {%8,%9}, {%0,%1,%2,%3};"
        : "+f"(c[0]), "+f"(c[1]), "+f"(c[2]), "+f"(c[3])
        : "r"(a.x), "r"(a.y), "r"(a.z), "r"(a.w), "r"(b0), "r"(b1));
}

// -------------------- weight packing (fragment-major fp16) -------------------
__global__ void pack_weights_kernel(const float* __restrict__ Wself,
                                    const float* __restrict__ Wrel) {
    int idx = blockIdx.x * blockDim.x + threadIdx.x;
    const int per_layer = NCOL * DIMS;
    const int total = NLAYER * per_layer;
    if (idx >= total) return;
    int l  = idx / per_layer;
    int hf = idx - l * per_layer;
    int e    = hf & 1;
    int w    = (hf >> 1) & 3;
    int lane = (hf >> 3) & 31;
    int kp2  = (hf >> 8) & 3;
    int cj   = (hf >> 10) & 15;
    int t    = hf >> 14;
    int qid = lane >> 2, rid = lane & 3;
    int kp   = kp2 * 2 + (w >> 1);
    int pair = w & 1;
    int k = kp * 16 + pair * 8 + rid * 2 + e;
    int n = t * 128 + cj * 8 + qid;
    float v;
    if (n < DIMS) {
        v = Wself[(l * DIMS + k) * DIMS + n];
    } else {
        int r = (n - DIMS) >> 7;
        int ee = (n - DIMS) & 127;
        v = Wrel[(((size_t)(l * NRELS + r) * DIMS) + k) * DIMS + ee];
    }
    g_Bpack[l][hf] = __float2half_rn(v);
}

// -------------------- edge prep ----------------------------------------------
__global__ void zero_prep_kernel() {
    int i = blockIdx.x * blockDim.x + threadIdx.x;
    if (i < NNODES * NRELS) g_cnt[i] = 0;
    if (i < NNODES) g_deg[i] = 0;
}

__global__ void hist_kernel(const int* __restrict__ dst, const int* __restrict__ et) {
    int e = blockIdx.x * blockDim.x + threadIdx.x;
    if (e >= NEDGE) return;
    int d = dst[e];
    atomicAdd(&g_cnt[d * NRELS + et[e]], 1);
    atomicAdd(&g_deg[d], 1);
}

// hierarchical scan: A) per-block inclusive scan; B) scan block totals; C) add
__global__ void scanA_kernel() {
    __shared__ int s[1024];
    int t = threadIdx.x;
    int i = blockIdx.x * 1024 + t;
    int v = (i < NNODES) ? g_deg[i] : 0;
    s[t] = v;
    __syncthreads();
#pragma unroll
    for (int off = 1; off < 1024; off <<= 1) {
        int x = (t >= off) ? s[t - off] : 0;
        __syncthreads();
        s[t] += x;
        __syncthreads();
    }
    if (i < NNODES) g_off[i + 1] = s[t];
    if (t == 1023) g_bt[blockIdx.x] = s[t];
}

__global__ void scanB_kernel() {
    if (threadIdx.x == 0) {
        int run = 0;
        for (int b = 0; b < SCANB; b++) {
            int v = g_bt[b];
            g_bt[b] = run;          // exclusive
            run += v;
        }
    }
}

__global__ void scanC_kernel() {
    int t = threadIdx.x;
    int i = blockIdx.x * 1024 + t;
    if (i == 0) g_off[0] = 0;
    if (i < NNODES) {
        int o = g_off[i + 1] + g_bt[blockIdx.x];
        g_off[i + 1] = o;
        g_cur[i] = o - g_deg[i];    // bucket start
    }
}

__global__ void scatter_kernel(const int* __restrict__ src,
                               const int* __restrict__ dst,
                               const int* __restrict__ et) {
    int e = blockIdx.x * blockDim.x + threadIdx.x;
    if (e >= NEDGE) return;
    int d = dst[e];
    int pos = atomicAdd(&g_cur[d], 1);
    g_epack[pos] = (uint32_t)src[e] | ((uint32_t)et[e] << 16);
}

// -------------------- grouped aggregation (no atomics) -----------------------
__global__ void __launch_bounds__(256)
group_agg_kernel(float* __restrict__ hn) {
    int warp = (blockIdx.x * blockDim.x + threadIdx.x) >> 5;
    int lane = threadIdx.x & 31;
    if (warp >= NNODES) return;
    int beg = g_off[warp];
    int end = g_off[warp + 1];
    if (beg == end) return;

    float4 acc = make_float4(0.f, 0.f, 0.f, 0.f);
    uint32_t p = g_epack[beg];
    for (int i = beg; i < end; i++) {
        uint32_t pn = (i + 1 < end) ? g_epack[i + 1] : 0u;
        int s = p & 0xFFFF;
        int r = p >> 16;
        float w = 1.0f / (float)g_cnt[warp * NRELS + r];
        uint2 u = *reinterpret_cast<const uint2*>(
            g_T + (size_t)s * TCOL + r * DIMS + lane * 4);
        float2 f0 = __half22float2(*reinterpret_cast<__half2*>(&u.x));
        float2 f1 = __half22float2(*reinterpret_cast<__half2*>(&u.y));
        acc.x += w * f0.x; acc.y += w * f0.y;
        acc.z += w * f1.x; acc.w += w * f1.y;
        p = pn;
    }
    float* o = hn + (size_t)warp * DIMS + lane * 4;
    float4 cur = *reinterpret_cast<float4*>(o);
    cur.x += acc.x; cur.y += acc.y; cur.z += acc.z; cur.w += acc.w;
    *reinterpret_cast<float4*>(o) = cur;
}

// -------------------- A conversion to fragment-major fp16 --------------------
// one block per M tile: coalesced load (+gather/relu) to smem, permute-write
__global__ void __launch_bounds__(512)
convA_kernel(const float* __restrict__ A,
             const int* __restrict__ nid,
             const float* __restrict__ emb,
             int relu_a) {
    extern __shared__ float scr[];      // 128 x 128 fp32
    const int tid = threadIdx.x;
    const int m0 = blockIdx.x * 128;

    for (int i = tid; i < 128 * 32; i += 512) {
        int r = i >> 5, c4 = i & 31;
        const float* arow;
        if (nid) {
            int m = m0 + r;
            int id = nid[m < NNODES ? m : NNODES - 1];
            arow = emb + (size_t)id * DIMS;
        } else {
            arow = A + (size_t)(m0 + r) * DIMS;
        }
        float4 v = reinterpret_cast<const float4*>(arow)[c4];
        if (relu_a) {
            v.x = fmaxf(v.x, 0.f); v.y = fmaxf(v.y, 0.f);
            v.z = fmaxf(v.z, 0.f); v.w = fmaxf(v.w, 0.f);
        }
        *reinterpret_cast<float4*>(&scr[r * 128 + c4 * 4]) = v;
    }
    __syncthreads();

    uint4* outp = g_Afrag + (size_t)blockIdx.x * 2048;
#pragma unroll
    for (int it = 0; it < 4; it++) {
        int item = tid + it * 512;
        int bi = item >> 8;
        int kk = (item >> 5) & 7;
        int ln = item & 31;
        int q = ln >> 2, rd = ln & 3;
        int r0 = bi * 16 + q;
        int c0 = kk * 16 + rd * 2;
        uint4 w;
        w.x = pack_h2(scr[r0 * 128 + c0],           scr[r0 * 128 + c0 + 1]);
        w.y = pack_h2(scr[(r0 + 8) * 128 + c0],     scr[(r0 + 8) * 128 + c0 + 1]);
        w.z = pack_h2(scr[r0 * 128 + c0 + 8],       scr[r0 * 128 + c0 + 9]);
        w.w = pack_h2(scr[(r0 + 8) * 128 + c0 + 8], scr[(r0 + 8) * 128 + c0 + 9]);
        outp[item] = w;
    }
}

// -------------------- B-stationary GEMM ---------------------------------------
// grid (17 N-tiles, 17 M-groups). Block: B tile in regs (per warp), stream 23
// A tiles (fragment-major fp16, cp.async double-buffered).
// smem: A0 [0,32K) | A1 [32K,64K) | B [64K,96K)
#define GEMM_SMEM 98304

__global__ void __launch_bounds__(512, 1)
gemm_kernel(const uint4* __restrict__ Afrag,
            const __half* __restrict__ B,
            __half* __restrict__ T,
            float* __restrict__ hn) {
    extern __shared__ char smc[];
    uint4* As[2] = { reinterpret_cast<uint4*>(smc),
                     reinterpret_cast<uint4*>(smc + 32768) };
    uint4* Bsm   = reinterpret_cast<uint4*>(smc + 65536);
    const uint32_t sb = smem_u32(smc);

    const int tid = threadIdx.x;
    const int nt = blockIdx.x;          // 0..16
    const int mg = blockIdx.y;          // 0..16
    const int mt0 = mg * MGROUP;

    // group 0: B tile
    {
        const __half* Bt = B + (size_t)nt * TILE_HALVES;
        uint32_t sbase = sb + 65536u;
#pragma unroll
        for (int it = 0; it < 4; it++) {
            int i = tid + it * 512;
            cp_async16(sbase + (uint32_t)i * 16u, Bt + i * 8);
        }
        CP_COMMIT();
    }
    // group 1: A tile 0
    {
        const uint4* At = Afrag + (size_t)mt0 * 2048;
#pragma unroll
        for (int it = 0; it < 4; it++) {
            int i = tid + it * 512;
            cp_async16(sb + (uint32_t)i * 16u, At + i);
        }
        CP_COMMIT();
    }
    CP_WAIT1();             // B done (A0 may still be in flight)
    __syncthreads();

    const int wid  = tid >> 5;
    const int wm   = wid & 3;          // 4 warp rows (32 M each)
    const int wn   = wid >> 2;         // 4 warp cols (32 N each)
    const int lane = tid & 31;
    const int qid  = lane >> 2;
    const int rid  = lane & 3;

    // hoist B fragments to registers (reused across all 23 M tiles)
    uint4 bfr[4][4];
#pragma unroll
    for (int jn = 0; jn < 4; jn++)
#pragma unroll
        for (int kp2 = 0; kp2 < 4; kp2++)
            bfr[jn][kp2] = Bsm[(((wn * 4 + jn) * 4 + kp2) << 5) + lane];

    const int gc0 = nt * 128 + wn * 32;   // warp's first global col

    for (int mi = 0; mi < MGROUP; mi++) {
        const uint4* Acur = As[mi & 1];
        if (mi + 1 < MGROUP) {
            const uint4* At = Afrag + (size_t)(mt0 + mi + 1) * 2048;
            uint32_t sbase = sb + (uint32_t)((mi + 1) & 1) * 32768u;
#pragma unroll
            for (int it = 0; it < 4; it++) {
                int i = tid + it * 512;
                cp_async16(sbase + (uint32_t)i * 16u, At + i);
            }
            CP_COMMIT();
            CP_WAIT1();     // current tile's group complete
        } else {
            CP_WAIT0();
        }
        __syncthreads();    // current A visible to all warps

        float c[2][4][4];
#pragma unroll
        for (int im = 0; im < 2; im++)
#pragma unroll
            for (int jn = 0; jn < 4; jn++)
#pragma unroll
                for (int q = 0; q < 4; q++) c[im][jn][q] = 0.f;

#pragma unroll
        for (int kk = 0; kk < 8; kk++) {
            uint4 af[2];
            af[0] = Acur[(((wm * 2 + 0) * 8 + kk) << 5) + lane];
            af[1] = Acur[(((wm * 2 + 1) * 8 + kk) << 5) + lane];
            int kp2 = kk >> 1;
            int sub = kk & 1;
#pragma unroll
            for (int im = 0; im < 2; im++)
#pragma unroll
                for (int jn = 0; jn < 4; jn++) {
                    uint32_t b0 = sub ? bfr[jn][kp2].z : bfr[jn][kp2].x;
                    uint32_t b1 = sub ? bfr[jn][kp2].w : bfr[jn][kp2].y;
                    mma_f16(c[im][jn], af[im], b0, b1);
                }
        }

        // epilogue
        const int m0 = (mt0 + mi) * 128;
        if (nt == 0) {
#pragma unroll
            for (int im = 0; im < 2; im++) {
                int row = m0 + wm * 32 + im * 16 + qid;
#pragma unroll
                for (int jn = 0; jn < 4; jn++) {
                    int col = gc0 + jn * 8 + 2 * rid;
                    *reinterpret_cast<float2*>(hn + (size_t)row * DIMS + col)
                        = make_float2(c[im][jn][0], c[im][jn][1]);
                    *reinterpret_cast<float2*>(hn + (size_t)(row + 8) * DIMS + col)
                        = make_float2(c[im][jn][2], c[im][jn][3]);
                }
            }
        } else {
            int cb = gc0 - DIMS;
#pragma unroll
            for (int im = 0; im < 2; im++) {
                int row = m0 + wm * 32 + im * 16 + qid;
#pragma unroll
                for (int jn = 0; jn < 4; jn++) {
                    int col = cb + jn * 8 + 2 * rid;
                    *reinterpret_cast<__half2*>(T + (size_t)row * TCOL + col)
                        = __floats2half2_rn(c[im][jn][0], c[im][jn][1]);
                    *reinterpret_cast<__half2*>(T + (size_t)(row + 8) * TCOL + col)
                        = __floats2half2_rn(c[im][jn][2], c[im][jn][3]);
                }
            }
        }
        __syncthreads();    // all reads of Acur done before it is refilled
    }
}

// -------------------- scoring (relu fused) -----------------------------------
__global__ void score_kernel(const float* __restrict__ h,
                             const int* __restrict__ heads,
                             const int* __restrict__ rels,
                             const int* __restrict__ tails,
                             const float* __restrict__ rel_emb,
                             const float* __restrict__ path_feat,
                             const int* __restrict__ task_idx,
                             const float* __restrict__ delta_w,
                             const float* __restrict__ lambda_logit,
                             const float* __restrict__ rule_init,
                             float* __restrict__ out) {
    int warp = (blockIdx.x * blockDim.x + threadIdx.x) >> 5;
    int lane = threadIdx.x & 31;
    if (warp >= NQUERY) return;
    int hh = heads[warp], rr = rels[warp], tt = tails[warp];
    float4 a = reinterpret_cast<const float4*>(h + (size_t)hh * DIMS)[lane];
    float4 r = reinterpret_cast<const float4*>(rel_emb + (size_t)rr * DIMS)[lane];
    float4 b = reinterpret_cast<const float4*>(h + (size_t)tt * DIMS)[lane];
    a.x = fmaxf(a.x, 0.f); a.y = fmaxf(a.y, 0.f); a.z = fmaxf(a.z, 0.f); a.w = fmaxf(a.w, 0.f);
    b.x = fmaxf(b.x, 0.f); b.y = fmaxf(b.y, 0.f); b.z = fmaxf(b.z, 0.f); b.w = fmaxf(b.w, 0.f);
    float s = a.x * r.x * b.x + a.y * r.y * b.y + a.z * r.z * b.z + a.w * r.w * b.w;
#pragma unroll
    for (int off = 16; off > 0; off >>= 1)
        s += __shfl_xor_sync(0xFFFFFFFFu, s, off);
    if (lane == 0) {
        int idx = task_idx[0];
        float sp = 0.f;
#pragma unroll
        for (int p = 0; p < PDIM; p++)
            sp += path_feat[warp * PDIM + p] * (rule_init[idx * PDIM + p] + delta_w[idx * PDIM + p]);
        float lam = 1.0f / (1.0f + __expf(-lambda_logit[idx]));
        out[warp] = lam * s + (1.0f - lam) * sp;
    }
}

// -------------------- launcher -----------------------------------------------
extern "C" void kernel_launch(void* const* d_in, const int* in_sizes, int n_in,
                              void* d_out, int out_size) {
    const int*   node_ids   = (const int*)d_in[0];
    const int*   edge_index = (const int*)d_in[1];
    const int*   edge_type  = (const int*)d_in[2];
    const int*   heads      = (const int*)d_in[3];
    const int*   rels       = (const int*)d_in[4];
    const int*   tails      = (const int*)d_in[5];
    const float* path_feat  = (const float*)d_in[6];
    const int*   task_idx   = (const int*)d_in[7];
    const float* entity_emb = (const float*)d_in[8];
    const float* rel_emb    = (const float*)d_in[9];
    const float* W_self     = (const float*)d_in[10];
    const float* W_rel      = (const float*)d_in[11];
    const float* delta_w    = (const float*)d_in[12];
    const float* lambda_lg  = (const float*)d_in[13];
    const float* rule_init  = (const float*)d_in[14];
    float*       out        = (float*)d_out;

    const int* src = edge_index;
    const int* dst = edge_index + NEDGE;

    float *hA, *hB;
    __half *T, *Bpack;
    uint4* Afrag;
    cudaGetSymbolAddress((void**)&hA, g_hA);
    cudaGetSymbolAddress((void**)&hB, g_hB);
    cudaGetSymbolAddress((void**)&T, g_T);
    cudaGetSymbolAddress((void**)&Bpack, g_Bpack);
    cudaGetSymbolAddress((void**)&Afrag, g_Afrag);

    const int TPB = 256;
    cudaFuncSetAttribute(gemm_kernel,
                         cudaFuncAttributeMaxDynamicSharedMemorySize, GEMM_SMEM);
    cudaFuncSetAttribute(convA_kernel,
                         cudaFuncAttributeMaxDynamicSharedMemorySize, 65536);

    // prep (topology + weights, once)
    pack_weights_kernel<<<(NLAYER * NCOL * DIMS + TPB - 1) / TPB, TPB>>>(W_self, W_rel);
    zero_prep_kernel<<<(NNODES * NRELS + TPB - 1) / TPB, TPB>>>();
    hist_kernel<<<(NEDGE + TPB - 1) / TPB, TPB>>>(dst, edge_type);
    scanA_kernel<<<SCANB, 1024>>>();
    scanB_kernel<<<1, 32>>>();
    scanC_kernel<<<SCANB, 1024>>>();
    scatter_kernel<<<(NEDGE + TPB - 1) / TPB, TPB>>>(src, dst, edge_type);

    dim3 ggrid(NTILES, NTILES);   // 17 x 17
    const int agg_blocks = (NNODES * 32 + TPB - 1) / TPB;

    // layer 1
    convA_kernel<<<MTILES, 512, 65536>>>(nullptr, node_ids, entity_emb, 0);
    gemm_kernel<<<ggrid, 512, GEMM_SMEM>>>(Afrag, Bpack, T, hB);
    group_agg_kernel<<<agg_blocks, TPB>>>(hB);
    // layer 2
    convA_kernel<<<MTILES, 512, 65536>>>(hB, nullptr, nullptr, 1);
    gemm_kernel<<<ggrid, 512, GEMM_SMEM>>>(Afrag, Bpack + (size_t)NCOL * DIMS, T, hA);
    group_agg_kernel<<<agg_blocks, TPB>>>(hA);

    score_kernel<<<(NQUERY * 32 + TPB - 1) / TPB, TPB>>>(
        hA, heads, rels, tails, rel_emb, path_feat, task_idx,
        delta_w, lambda_lg, rule_init, out);
}

// round 11
// speedup vs baseline: 5.6751x; 1.0822x over previous
#include <cuda_runtime.h>
#include <cuda_fp16.h>
#include <cstdint>

#define NNODES 50000
#define MPAD   50048            // 391 * 128
#define NRELS  16
#define DIMS   128
#define NLAYER 2
#define NEDGE  600000
#define NQUERY 8192
#define PDIM   5
#define NCOL   (DIMS * (NRELS + 1))   // 2176
#define TCOL   (DIMS * NRELS)         // 2048
#define NTILES 17
#define MTILES 391                    // 17 * 23
#define MGROUP 23                     // M tiles per GEMM block
#define TILE_HALVES (128 * 128)       // fp16 per B tile (32 KB)
#define SCANB  49                     // scan blocks

// -------------------- scratch ------------------------------------------------
__device__ float  g_hA[(size_t)MPAD * DIMS];
__device__ float  g_hB[(size_t)MPAD * DIMS];
__device__ __half g_T[(size_t)MPAD * TCOL];
__device__ __half g_Bpack[NLAYER][(size_t)NCOL * DIMS];   // fragment-major fp16
__device__ uint4  g_Afrag[(size_t)MTILES * 2048];         // fragment-major fp16 A
__device__ int    g_cnt[NNODES * NRELS];
__device__ int    g_deg[NNODES];
__device__ int    g_off[NNODES + 1];
__device__ int    g_cur[NNODES];
__device__ int    g_bt[SCANB + 1];
__device__ uint32_t g_epack[NEDGE];   // src | (rel<<16)

// -------------------- helpers ------------------------------------------------
__device__ __forceinline__ uint32_t smem_u32(const void* p) {
    uint32_t a;
    asm("{ .reg .u64 t; cvta.to.shared.u64 t, %1; cvt.u32.u64 %0, t; }" : "=r"(a) : "l"(p));
    return a;
}
__device__ __forceinline__ void cp_async16(uint32_t saddr, const void* g) {
    asm volatile("cp.async.ca.shared.global [%0], [%1], 16;" :: "r"(saddr), "l"(g));
}
#define CP_COMMIT() asm volatile("cp.async.commit_group;")
#define CP_WAIT0()  asm volatile("cp.async.wait_group 0;")
#define CP_WAIT1()  asm volatile("cp.async.wait_group 1;")

__device__ __forceinline__ uint32_t pack_h2(float a, float b) {
    __half2 h = __floats2half2_rn(a, b);
    return *reinterpret_cast<uint32_t*>(&h);
}
__device__ __forceinline__ void mma_f16(float c[4], uint4 a, uint32_t b0, uint32_t b1) {
    asm volatile(
        "mma.sync.aligned.m16n8k16.row.col.f32.f16.f16.f32 "
        "{%0,%1,%2,%3}, {%4,%5,%6,%7}, {%8,%9}, {%0,%1,%2,%3};"
        : "+f"(c[0]), "+f"(c[1]), "+f"(c[2]), "+f"(c[3])
        : "r"(a.x), "r"(a.y), "r"(a.z), "r"(a.w), "r"(b0), "r"(b1));
}

// -------------------- fused prep: weight packing + zero init ------------------
__global__ void prep_kernel(const float* __restrict__ Wself,
                            const float* __restrict__ Wrel) {
    int idx = blockIdx.x * blockDim.x + threadIdx.x;
    const int per_layer = NCOL * DIMS;
    const int total_pack = NLAYER * per_layer;       // 557056
    if (idx < total_pack) {
        int l  = idx / per_layer;
        int hf = idx - l * per_layer;
        int e    = hf & 1;
        int w    = (hf >> 1) & 3;
        int lane = (hf >> 3) & 31;
        int kp2  = (hf >> 8) & 3;
        int cj   = (hf >> 10) & 15;
        int t    = hf >> 14;
        int qid = lane >> 2, rid = lane & 3;
        int kp   = kp2 * 2 + (w >> 1);
        int pair = w & 1;
        int k = kp * 16 + pair * 8 + rid * 2 + e;
        int n = t * 128 + cj * 8 + qid;
        float v;
        if (n < DIMS) {
            v = Wself[(l * DIMS + k) * DIMS + n];
        } else {
            int r = (n - DIMS) >> 7;
            int ee = (n - DIMS) & 127;
            v = Wrel[(((size_t)(l * NRELS + r) * DIMS) + k) * DIMS + ee];
        }
        g_Bpack[l][hf] = __float2half_rn(v);
    }
    if (idx < NNODES * NRELS) g_cnt[idx] = 0;
    if (idx < NNODES) g_deg[idx] = 0;
}

__global__ void hist_kernel(const int* __restrict__ dst, const int* __restrict__ et) {
    int e = blockIdx.x * blockDim.x + threadIdx.x;
    if (e >= NEDGE) return;
    int d = dst[e];
    atomicAdd(&g_cnt[d * NRELS + et[e]], 1);
    atomicAdd(&g_deg[d], 1);
}

// hierarchical scan
__global__ void scanA_kernel() {
    __shared__ int s[1024];
    int t = threadIdx.x;
    int i = blockIdx.x * 1024 + t;
    int v = (i < NNODES) ? g_deg[i] : 0;
    s[t] = v;
    __syncthreads();
#pragma unroll
    for (int off = 1; off < 1024; off <<= 1) {
        int x = (t >= off) ? s[t - off] : 0;
        __syncthreads();
        s[t] += x;
        __syncthreads();
    }
    if (i < NNODES) g_off[i + 1] = s[t];
    if (t == 1023) g_bt[blockIdx.x] = s[t];
}

__global__ void scanB_kernel() {
    if (threadIdx.x == 0) {
        int run = 0;
        for (int b = 0; b < SCANB; b++) {
            int v = g_bt[b];
            g_bt[b] = run;
            run += v;
        }
    }
}

__global__ void scanC_kernel() {
    int t = threadIdx.x;
    int i = blockIdx.x * 1024 + t;
    if (i == 0) g_off[0] = 0;
    if (i < NNODES) {
        int o = g_off[i + 1] + g_bt[blockIdx.x];
        g_off[i + 1] = o;
        g_cur[i] = o - g_deg[i];
    }
}

__global__ void scatter_kernel(const int* __restrict__ src,
                               const int* __restrict__ dst,
                               const int* __restrict__ et) {
    int e = blockIdx.x * blockDim.x + threadIdx.x;
    if (e >= NEDGE) return;
    int d = dst[e];
    int pos = atomicAdd(&g_cur[d], 1);
    g_epack[pos] = (uint32_t)src[e] | ((uint32_t)et[e] << 16);
}

// -------------------- grouped aggregation v2 (lane-parallel, no atomics) -----
// one warp per dst. Lane i holds epack[beg+i]; shfl broadcasts give all T-row
// addresses immediately -> MLP ~= degree. Per-rel 1/cnt preloaded via shfl.
__global__ void __launch_bounds__(256)
group_agg_kernel(float* __restrict__ hn) {
    int warp = (blockIdx.x * blockDim.x + threadIdx.x) >> 5;
    int lane = threadIdx.x & 31;
    if (warp >= NNODES) return;
    int beg = g_off[warp];
    int end = g_off[warp + 1];
    if (beg == end) return;

    // lane r (<16) holds 1/cnt for relation r
    float inv = 0.f;
    if (lane < NRELS) {
        int c = g_cnt[warp * NRELS + lane];
        inv = (c > 0) ? (1.0f / (float)c) : 0.f;
    }

    float4 acc = make_float4(0.f, 0.f, 0.f, 0.f);
    for (int base = beg; base < end; base += 32) {
        int m = min(32, end - base);
        uint32_t myp = (lane < m) ? g_epack[base + lane] : 0u;
        for (int i = 0; i < m; i++) {
            uint32_t p = __shfl_sync(0xFFFFFFFFu, myp, i);
            int s = p & 0xFFFF;
            int r = p >> 16;
            float w = __shfl_sync(0xFFFFFFFFu, inv, r);
            uint2 u = *reinterpret_cast<const uint2*>(
                g_T + (size_t)s * TCOL + r * DIMS + lane * 4);
            float2 f0 = __half22float2(*reinterpret_cast<__half2*>(&u.x));
            float2 f1 = __half22float2(*reinterpret_cast<__half2*>(&u.y));
            acc.x += w * f0.x; acc.y += w * f0.y;
            acc.z += w * f1.x; acc.w += w * f1.y;
        }
    }
    float* o = hn + (size_t)warp * DIMS + lane * 4;
    float4 cur = *reinterpret_cast<float4*>(o);
    cur.x += acc.x; cur.y += acc.y; cur.z += acc.z; cur.w += acc.w;
    *reinterpret_cast<float4*>(o) = cur;
}

// -------------------- A conversion to fragment-major fp16 --------------------
__global__ void __launch_bounds__(512)
convA_kernel(const float* __restrict__ A,
             const int* __restrict__ nid,
             const float* __restrict__ emb,
             int relu_a) {
    extern __shared__ float scr[];
    const int tid = threadIdx.x;
    const int m0 = blockIdx.x * 128;

    for (int i = tid; i < 128 * 32; i += 512) {
        int r = i >> 5, c4 = i & 31;
        const float* arow;
        if (nid) {
            int m = m0 + r;
            int id = nid[m < NNODES ? m : NNODES - 1];
            arow = emb + (size_t)id * DIMS;
        } else {
            arow = A + (size_t)(m0 + r) * DIMS;
        }
        float4 v = reinterpret_cast<const float4*>(arow)[c4];
        if (relu_a) {
            v.x = fmaxf(v.x, 0.f); v.y = fmaxf(v.y, 0.f);
            v.z = fmaxf(v.z, 0.f); v.w = fmaxf(v.w, 0.f);
        }
        *reinterpret_cast<float4*>(&scr[r * 128 + c4 * 4]) = v;
    }
    __syncthreads();

    uint4* outp = g_Afrag + (size_t)blockIdx.x * 2048;
#pragma unroll
    for (int it = 0; it < 4; it++) {
        int item = tid + it * 512;
        int bi = item >> 8;
        int kk = (item >> 5) & 7;
        int ln = item & 31;
        int q = ln >> 2, rd = ln & 3;
        int r0 = bi * 16 + q;
        int c0 = kk * 16 + rd * 2;
        uint4 w;
        w.x = pack_h2(scr[r0 * 128 + c0],           scr[r0 * 128 + c0 + 1]);
        w.y = pack_h2(scr[(r0 + 8) * 128 + c0],     scr[(r0 + 8) * 128 + c0 + 1]);
        w.z = pack_h2(scr[r0 * 128 + c0 + 8],       scr[r0 * 128 + c0 + 9]);
        w.w = pack_h2(scr[(r0 + 8) * 128 + c0 + 8], scr[(r0 + 8) * 128 + c0 + 9]);
        outp[item] = w;
    }
}

// -------------------- B-stationary GEMM ---------------------------------------
#define GEMM_SMEM 98304

__global__ void __launch_bounds__(512, 1)
gemm_kernel(const uint4* __restrict__ Afrag,
            const __half* __restrict__ B,
            __half* __restrict__ T,
            float* __restrict__ hn) {
    extern __shared__ char smc[];
    uint4* As[2] = { reinterpret_cast<uint4*>(smc),
                     reinterpret_cast<uint4*>(smc + 32768) };
    uint4* Bsm   = reinterpret_cast<uint4*>(smc + 65536);
    const uint32_t sb = smem_u32(smc);

    const int tid = threadIdx.x;
    const int nt = blockIdx.x;
    const int mg = blockIdx.y;
    const int mt0 = mg * MGROUP;

    {
        const __half* Bt = B + (size_t)nt * TILE_HALVES;
        uint32_t sbase = sb + 65536u;
#pragma unroll
        for (int it = 0; it < 4; it++) {
            int i = tid + it * 512;
            cp_async16(sbase + (uint32_t)i * 16u, Bt + i * 8);
        }
        CP_COMMIT();
    }
    {
        const uint4* At = Afrag + (size_t)mt0 * 2048;
#pragma unroll
        for (int it = 0; it < 4; it++) {
            int i = tid + it * 512;
            cp_async16(sb + (uint32_t)i * 16u, At + i);
        }
        CP_COMMIT();
    }
    CP_WAIT1();
    __syncthreads();

    const int wid  = tid >> 5;
    const int wm   = wid & 3;
    const int wn   = wid >> 2;
    const int lane = tid & 31;
    const int qid  = lane >> 2;
    const int rid  = lane & 3;

    uint4 bfr[4][4];
#pragma unroll
    for (int jn = 0; jn < 4; jn++)
#pragma unroll
        for (int kp2 = 0; kp2 < 4; kp2++)
            bfr[jn][kp2] = Bsm[(((wn * 4 + jn) * 4 + kp2) << 5) + lane];

    const int gc0 = nt * 128 + wn * 32;

    for (int mi = 0; mi < MGROUP; mi++) {
        const uint4* Acur = As[mi & 1];
        if (mi + 1 < MGROUP) {
            const uint4* At = Afrag + (size_t)(mt0 + mi + 1) * 2048;
            uint32_t sbase = sb + (uint32_t)((mi + 1) & 1) * 32768u;
#pragma unroll
            for (int it = 0; it < 4; it++) {
                int i = tid + it * 512;
                cp_async16(sbase + (uint32_t)i * 16u, At + i);
            }
            CP_COMMIT();
            CP_WAIT1();
        } else {
            CP_WAIT0();
        }
        __syncthreads();

        float c[2][4][4];
#pragma unroll
        for (int im = 0; im < 2; im++)
#pragma unroll
            for (int jn = 0; jn < 4; jn++)
#pragma unroll
                for (int q = 0; q < 4; q++) c[im][jn][q] = 0.f;

#pragma unroll
        for (int kk = 0; kk < 8; kk++) {
            uint4 af[2];
            af[0] = Acur[(((wm * 2 + 0) * 8 + kk) << 5) + lane];
            af[1] = Acur[(((wm * 2 + 1) * 8 + kk) << 5) + lane];
            int kp2 = kk >> 1;
            int sub = kk & 1;
#pragma unroll
            for (int im = 0; im < 2; im++)
#pragma unroll
                for (int jn = 0; jn < 4; jn++) {
                    uint32_t b0 = sub ? bfr[jn][kp2].z : bfr[jn][kp2].x;
                    uint32_t b1 = sub ? bfr[jn][kp2].w : bfr[jn][kp2].y;
                    mma_f16(c[im][jn], af[im], b0, b1);
                }
        }

        const int m0 = (mt0 + mi) * 128;
        if (nt == 0) {
#pragma unroll
            for (int im = 0; im < 2; im++) {
                int row = m0 + wm * 32 + im * 16 + qid;
#pragma unroll
                for (int jn = 0; jn < 4; jn++) {
                    int col = gc0 + jn * 8 + 2 * rid;
                    *reinterpret_cast<float2*>(hn + (size_t)row * DIMS + col)
                        = make_float2(c[im][jn][0], c[im][jn][1]);
                    *reinterpret_cast<float2*>(hn + (size_t)(row + 8) * DIMS + col)
                        = make_float2(c[im][jn][2], c[im][jn][3]);
                }
            }
        } else {
            int cb = gc0 - DIMS;
#pragma unroll
            for (int im = 0; im < 2; im++) {
                int row = m0 + wm * 32 + im * 16 + qid;
#pragma unroll
                for (int jn = 0; jn < 4; jn++) {
                    int col = cb + jn * 8 + 2 * rid;
                    *reinterpret_cast<__half2*>(T + (size_t)row * TCOL + col)
                        = __floats2half2_rn(c[im][jn][0], c[im][jn][1]);
                    *reinterpret_cast<__half2*>(T + (size_t)(row + 8) * TCOL + col)
                        = __floats2half2_rn(c[im][jn][2], c[im][jn][3]);
                }
            }
        }
        __syncthreads();
    }
}

// -------------------- scoring (relu fused) -----------------------------------
__global__ void score_kernel(const float* __restrict__ h,
                             const int* __restrict__ heads,
                             const int* __restrict__ rels,
                             const int* __restrict__ tails,
                             const float* __restrict__ rel_emb,
                             const float* __restrict__ path_feat,
                             const int* __restrict__ task_idx,
                             const float* __restrict__ delta_w,
                             const float* __restrict__ lambda_logit,
                             const float* __restrict__ rule_init,
                             float* __restrict__ out) {
    int warp = (blockIdx.x * blockDim.x + threadIdx.x) >> 5;
    int lane = threadIdx.x & 31;
    if (warp >= NQUERY) return;
    int hh = heads[warp], rr = rels[warp], tt = tails[warp];
    float4 a = reinterpret_cast<const float4*>(h + (size_t)hh * DIMS)[lane];
    float4 r = reinterpret_cast<const float4*>(rel_emb + (size_t)rr * DIMS)[lane];
    float4 b = reinterpret_cast<const float4*>(h + (size_t)tt * DIMS)[lane];
    a.x = fmaxf(a.x, 0.f); a.y = fmaxf(a.y, 0.f); a.z = fmaxf(a.z, 0.f); a.w = fmaxf(a.w, 0.f);
    b.x = fmaxf(b.x, 0.f); b.y = fmaxf(b.y, 0.f); b.z = fmaxf(b.z, 0.f); b.w = fmaxf(b.w, 0.f);
    float s = a.x * r.x * b.x + a.y * r.y * b.y + a.z * r.z * b.z + a.w * r.w * b.w;
#pragma unroll
    for (int off = 16; off > 0; off >>= 1)
        s += __shfl_xor_sync(0xFFFFFFFFu, s, off);
    if (lane == 0) {
        int idx = task_idx[0];
        float sp = 0.f;
#pragma unroll
        for (int p = 0; p < PDIM; p++)
            sp += path_feat[warp * PDIM + p] * (rule_init[idx * PDIM + p] + delta_w[idx * PDIM + p]);
        float lam = 1.0f / (1.0f + __expf(-lambda_logit[idx]));
        out[warp] = lam * s + (1.0f - lam) * sp;
    }
}

// -------------------- launcher -----------------------------------------------
extern "C" void kernel_launch(void* const* d_in, const int* in_sizes, int n_in,
                              void* d_out, int out_size) {
    const int*   node_ids   = (const int*)d_in[0];
    const int*   edge_index = (const int*)d_in[1];
    const int*   edge_type  = (const int*)d_in[2];
    const int*   heads      = (const int*)d_in[3];
    const int*   rels       = (const int*)d_in[4];
    const int*   tails      = (const int*)d_in[5];
    const float* path_feat  = (const float*)d_in[6];
    const int*   task_idx   = (const int*)d_in[7];
    const float* entity_emb = (const float*)d_in[8];
    const float* rel_emb    = (const float*)d_in[9];
    const float* W_self     = (const float*)d_in[10];
    const float* W_rel      = (const float*)d_in[11];
    const float* delta_w    = (const float*)d_in[12];
    const float* lambda_lg  = (const float*)d_in[13];
    const float* rule_init  = (const float*)d_in[14];
    float*       out        = (float*)d_out;

    const int* src = edge_index;
    const int* dst = edge_index + NEDGE;

    float *hA, *hB;
    __half *T, *Bpack;
    uint4* Afrag;
    cudaGetSymbolAddress((void**)&hA, g_hA);
    cudaGetSymbolAddress((void**)&hB, g_hB);
    cudaGetSymbolAddress((void**)&T, g_T);
    cudaGetSymbolAddress((void**)&Bpack, g_Bpack);
    cudaGetSymbolAddress((void**)&Afrag, g_Afrag);

    const int TPB = 256;
    cudaFuncSetAttribute(gemm_kernel,
                         cudaFuncAttributeMaxDynamicSharedMemorySize, GEMM_SMEM);
    cudaFuncSetAttribute(convA_kernel,
                         cudaFuncAttributeMaxDynamicSharedMemorySize, 65536);

    // prep (fused pack+zero, then topology sort)
    prep_kernel<<<(NNODES * NRELS + TPB - 1) / TPB, TPB>>>(W_self, W_rel);
    hist_kernel<<<(NEDGE + TPB - 1) / TPB, TPB>>>(dst, edge_type);
    scanA_kernel<<<SCANB, 1024>>>();
    scanB_kernel<<<1, 32>>>();
    scanC_kernel<<<SCANB, 1024>>>();
    scatter_kernel<<<(NEDGE + TPB - 1) / TPB, TPB>>>(src, dst, edge_type);

    dim3 ggrid(NTILES, NTILES);
    const int agg_blocks = (NNODES * 32 + TPB - 1) / TPB;

    // layer 1
    convA_kernel<<<MTILES, 512, 65536>>>(nullptr, node_ids, entity_emb, 0);
    gemm_kernel<<<ggrid, 512, GEMM_SMEM>>>(Afrag, Bpack, T, hB);
    group_agg_kernel<<<agg_blocks, TPB>>>(hB);
    // layer 2
    convA_kernel<<<MTILES, 512, 65536>>>(hB, nullptr, nullptr, 1);
    gemm_kernel<<<ggrid, 512, GEMM_SMEM>>>(Afrag, Bpack + (size_t)NCOL * DIMS, T, hA);
    group_agg_kernel<<<agg_blocks, TPB>>>(hA);

    score_kernel<<<(NQUERY * 32 + TPB - 1) / TPB, TPB>>>(
        hA, heads, rels, tails, rel_emb, path_feat, task_idx,
        delta_w, lambda_lg, rule_init, out);
}

// round 12
// speedup vs baseline: 5.8403x; 1.0291x over previous
#include <cuda_runtime.h>
#include <cuda_fp16.h>
#include <cstdint>

#define NNODES 50000
#define MPAD   50048            // 391 * 128
#define NRELS  16
#define DIMS   128
#define NLAYER 2
#define NEDGE  600000
#define NQUERY 8192
#define PDIM   5
#define NCOL   (DIMS * (NRELS + 1))   // 2176
#define TCOL   (DIMS * NRELS)         // 2048
#define NTILES 17
#define MTILES 391                    // 17 * 23
#define MGROUP 23                     // M tiles per GEMM block
#define TILE_HALVES (128 * 128)       // fp16 per B tile (32 KB)
#define SCANB  49

// -------------------- scratch ------------------------------------------------
__device__ float  g_hA[(size_t)MPAD * DIMS];
__device__ float  g_hB[(size_t)MPAD * DIMS];
__device__ __half g_Ah[(size_t)MPAD * DIMS];              // fp16 row-major staged A
__device__ __half g_T[(size_t)MPAD * TCOL];
__device__ __half g_Bpack[NLAYER][(size_t)NCOL * DIMS];   // fragment-major fp16
__device__ uint4  g_Afrag[(size_t)MTILES * 2048];         // fragment-major fp16 A
__device__ int    g_cnt[NNODES * NRELS];
__device__ int    g_deg[NNODES];
__device__ int    g_off[NNODES + 1];
__device__ int    g_cur[NNODES];
__device__ int    g_bt[SCANB + 1];
__device__ uint32_t g_epack[NEDGE];   // src | (rel<<16)

// -------------------- helpers ------------------------------------------------
__device__ __forceinline__ uint32_t smem_u32(const void* p) {
    uint32_t a;
    asm("{ .reg .u64 t; cvta.to.shared.u64 t, %1; cvt.u32.u64 %0, t; }" : "=r"(a) : "l"(p));
    return a;
}
__device__ __forceinline__ void cp_async16(uint32_t saddr, const void* g) {
    asm volatile("cp.async.ca.shared.global [%0], [%1], 16;" :: "r"(saddr), "l"(g));
}
#define CP_COMMIT() asm volatile("cp.async.commit_group;")
#define CP_WAIT0()  asm volatile("cp.async.wait_group 0;")
#define CP_WAIT1()  asm volatile("cp.async.wait_group 1;")
#define CP_WAIT2()  asm volatile("cp.async.wait_group 2;")
#define BAR_SYNC(id, cnt) asm volatile("bar.sync %0, %1;" :: "r"(id), "r"(cnt) : "memory")

__device__ __forceinline__ uint32_t pack_h2(float a, float b) {
    __half2 h = __floats2half2_rn(a, b);
    return *reinterpret_cast<uint32_t*>(&h);
}
__device__ __forceinline__ void mma_f16(float c[4], uint4 a, uint32_t b0, uint32_t b1) {
    asm volatile(
        "mma.sync.aligned.m16n8k16.row.col.f32.f16.f16.f32 "
        "{%0,%1,%2,%3}, {%4,%5,%6,%7}, {%8,%9}, {%0,%1,%2,%3};"
        : "+f"(c[0]), "+f"(c[1]), "+f"(c[2]), "+f"(c[3])
        : "r"(a.x), "r"(a.y), "r"(a.z), "r"(a.w), "r"(b0), "r"(b1));
}

// -------------------- fused prep: weight packing + zero init ------------------
__global__ void prep_kernel(const float* __restrict__ Wself,
                            const float* __restrict__ Wrel) {
    int idx = blockIdx.x * blockDim.x + threadIdx.x;
    const int per_layer = NCOL * DIMS;
    const int total_pack = NLAYER * per_layer;
    if (idx < total_pack) {
        int l  = idx / per_layer;
        int hf = idx - l * per_layer;
        int e    = hf & 1;
        int w    = (hf >> 1) & 3;
        int lane = (hf >> 3) & 31;
        int kp2  = (hf >> 8) & 3;
        int cj   = (hf >> 10) & 15;
        int t    = hf >> 14;
        int qid = lane >> 2, rid = lane & 3;
        int kp   = kp2 * 2 + (w >> 1);
        int pair = w & 1;
        int k = kp * 16 + pair * 8 + rid * 2 + e;
        int n = t * 128 + cj * 8 + qid;
        float v;
        if (n < DIMS) {
            v = Wself[(l * DIMS + k) * DIMS + n];
        } else {
            int r = (n - DIMS) >> 7;
            int ee = (n - DIMS) & 127;
            v = Wrel[(((size_t)(l * NRELS + r) * DIMS) + k) * DIMS + ee];
        }
        g_Bpack[l][hf] = __float2half_rn(v);
    }
    if (idx < NNODES * NRELS) g_cnt[idx] = 0;
    if (idx < NNODES) g_deg[idx] = 0;
}

__global__ void hist_kernel(const int* __restrict__ dst, const int* __restrict__ et) {
    int e = blockIdx.x * blockDim.x + threadIdx.x;
    if (e >= NEDGE) return;
    int d = dst[e];
    atomicAdd(&g_cnt[d * NRELS + et[e]], 1);
    atomicAdd(&g_deg[d], 1);
}

// hierarchical scan
__global__ void scanA_kernel() {
    __shared__ int s[1024];
    int t = threadIdx.x;
    int i = blockIdx.x * 1024 + t;
    int v = (i < NNODES) ? g_deg[i] : 0;
    s[t] = v;
    __syncthreads();
#pragma unroll
    for (int off = 1; off < 1024; off <<= 1) {
        int x = (t >= off) ? s[t - off] : 0;
        __syncthreads();
        s[t] += x;
        __syncthreads();
    }
    if (i < NNODES) g_off[i + 1] = s[t];
    if (t == 1023) g_bt[blockIdx.x] = s[t];
}

__global__ void scanB_kernel() {
    if (threadIdx.x == 0) {
        int run = 0;
        for (int b = 0; b < SCANB; b++) {
            int v = g_bt[b];
            g_bt[b] = run;
            run += v;
        }
    }
}

__global__ void scanC_kernel() {
    int t = threadIdx.x;
    int i = blockIdx.x * 1024 + t;
    if (i == 0) g_off[0] = 0;
    if (i < NNODES) {
        int o = g_off[i + 1] + g_bt[blockIdx.x];
        g_off[i + 1] = o;
        g_cur[i] = o - g_deg[i];
    }
}

__global__ void scatter_kernel(const int* __restrict__ src,
                               const int* __restrict__ dst,
                               const int* __restrict__ et) {
    int e = blockIdx.x * blockDim.x + threadIdx.x;
    if (e >= NEDGE) return;
    int d = dst[e];
    int pos = atomicAdd(&g_cur[d], 1);
    g_epack[pos] = (uint32_t)src[e] | ((uint32_t)et[e] << 16);
}

// -------------------- grouped aggregation (lane-parallel, no atomics) --------
// one warp per dst. If ah != null: write relu(self+agg) as fp16 rows (layer 1).
// Else: add agg into fp32 hn (layer 2).
__global__ void __launch_bounds__(256)
group_agg_kernel(float* __restrict__ hn, __half* __restrict__ ah) {
    int warp = (blockIdx.x * blockDim.x + threadIdx.x) >> 5;
    int lane = threadIdx.x & 31;
    if (warp >= NNODES) return;
    int beg = g_off[warp];
    int end = g_off[warp + 1];
    if (!ah && beg == end) return;     // fp32 row already holds self term

    float inv = 0.f;
    if (lane < NRELS) {
        int c = g_cnt[warp * NRELS + lane];
        inv = (c > 0) ? (1.0f / (float)c) : 0.f;
    }

    float4 acc = make_float4(0.f, 0.f, 0.f, 0.f);
    for (int base = beg; base < end; base += 32) {
        int m = min(32, end - base);
        uint32_t myp = (lane < m) ? g_epack[base + lane] : 0u;
        for (int i = 0; i < m; i++) {
            uint32_t p = __shfl_sync(0xFFFFFFFFu, myp, i);
            int s = p & 0xFFFF;
            int r = p >> 16;
            float w = __shfl_sync(0xFFFFFFFFu, inv, r);
            uint2 u = *reinterpret_cast<const uint2*>(
                g_T + (size_t)s * TCOL + r * DIMS + lane * 4);
            float2 f0 = __half22float2(*reinterpret_cast<__half2*>(&u.x));
            float2 f1 = __half22float2(*reinterpret_cast<__half2*>(&u.y));
            acc.x += w * f0.x; acc.y += w * f0.y;
            acc.z += w * f1.x; acc.w += w * f1.y;
        }
    }
    float* o = hn + (size_t)warp * DIMS + lane * 4;
    float4 cur = *reinterpret_cast<float4*>(o);
    cur.x += acc.x; cur.y += acc.y; cur.z += acc.z; cur.w += acc.w;
    if (ah) {
        cur.x = fmaxf(cur.x, 0.f); cur.y = fmaxf(cur.y, 0.f);
        cur.z = fmaxf(cur.z, 0.f); cur.w = fmaxf(cur.w, 0.f);
        uint2 h;
        h.x = pack_h2(cur.x, cur.y);
        h.y = pack_h2(cur.z, cur.w);
        *reinterpret_cast<uint2*>(ah + (size_t)warp * DIMS + lane * 4) = h;
    } else {
        *reinterpret_cast<float4*>(o) = cur;
    }
}

// -------------------- A conversion to fragment-major fp16 --------------------
// mode 0: gather fp32 rows from emb via nid (layer 1)
// mode 1: read fp16 rows from Ah (layer 2; relu already applied)
__global__ void __launch_bounds__(512)
convA_kernel(const __half* __restrict__ Ah,
             const int* __restrict__ nid,
             const float* __restrict__ emb,
             int mode) {
    extern __shared__ __half scrh[];   // 128 x 128 fp16 (32 KB)
    const int tid = threadIdx.x;
    const int m0 = blockIdx.x * 128;

    if (mode == 0) {
        for (int i = tid; i < 128 * 32; i += 512) {
            int r = i >> 5, c4 = i & 31;
            int m = m0 + r;
            int id = nid[m < NNODES ? m : NNODES - 1];
            float4 v = reinterpret_cast<const float4*>(emb + (size_t)id * DIMS)[c4];
            uint2 h;
            h.x = pack_h2(v.x, v.y);
            h.y = pack_h2(v.z, v.w);
            *reinterpret_cast<uint2*>(&scrh[r * 128 + c4 * 4]) = h;
        }
    } else {
        for (int i = tid; i < 128 * 16; i += 512) {
            int r = i >> 4, c8 = i & 15;
            uint4 v = reinterpret_cast<const uint4*>(Ah + (size_t)(m0 + r) * DIMS)[c8];
            *reinterpret_cast<uint4*>(&scrh[r * 128 + c8 * 8]) = v;
        }
    }
    __syncthreads();

    uint4* outp = g_Afrag + (size_t)blockIdx.x * 2048;
#pragma unroll
    for (int it = 0; it < 4; it++) {
        int item = tid + it * 512;
        int bi = item >> 8;
        int kk = (item >> 5) & 7;
        int ln = item & 31;
        int q = ln >> 2, rd = ln & 3;
        int r0 = bi * 16 + q;
        int c0 = kk * 16 + rd * 2;
        uint4 w;
        w.x = *reinterpret_cast<uint32_t*>(&scrh[r0 * 128 + c0]);
        w.y = *reinterpret_cast<uint32_t*>(&scrh[(r0 + 8) * 128 + c0]);
        w.z = *reinterpret_cast<uint32_t*>(&scrh[r0 * 128 + c0 + 8]);
        w.w = *reinterpret_cast<uint32_t*>(&scrh[(r0 + 8) * 128 + c0 + 8]);
        outp[item] = w;
    }
}

// -------------------- B-stationary GEMM, group-scoped pipeline ----------------
// 512 thr = 4 groups x 128 thr (4 warps). Group g owns M rows [g*32, g*32+32)
// of each 128-row tile, loads its own 8 KB A slice, syncs with bar.sync 1+g.
// 3-stage A pipeline, prefetch distance 2, issue AFTER the group barrier.
// smem: A[g][stage] = (g*3+stage)*8192, g<4,stage<3 (96 KB) | B at 98304 (32 KB)
#define GEMM_SMEM 131072

__global__ void __launch_bounds__(512, 1)
gemm_kernel(const uint4* __restrict__ Afrag,
            const __half* __restrict__ B,
            __half* __restrict__ T,
            float* __restrict__ hn) {
    extern __shared__ char smc[];
    uint4* Bsm = reinterpret_cast<uint4*>(smc + 98304);
    const uint32_t sb = smem_u32(smc);

    const int tid  = threadIdx.x;
    const int nt   = blockIdx.x;
    const int mg   = blockIdx.y;
    const int mt0  = mg * MGROUP;
    const int wid  = tid >> 5;
    const int grp  = wid >> 2;          // 0..3  (M strip)
    const int wn   = wid & 3;           // 0..3  (N strip)
    const int ltid = tid & 127;         // thread within group
    const int lane = tid & 31;
    const int qid  = lane >> 2;
    const int rid  = lane & 3;

    const uint32_t a_base = sb + (uint32_t)grp * 3u * 8192u;   // group's 3 stages
    const uint4* Atile    = Afrag + (size_t)grp * 512;          // group slice in tile

    // B tile (all threads)
    {
        const __half* Bt = B + (size_t)nt * TILE_HALVES;
#pragma unroll
        for (int it = 0; it < 4; it++) {
            int i = tid + it * 512;
            cp_async16(sb + 98304u + (uint32_t)i * 16u, Bt + i * 8);
        }
        CP_COMMIT();
    }
    // A slices for tiles 0,1 (group threads)
#pragma unroll
    for (int st = 0; st < 2; st++) {
        const uint4* At = Atile + (size_t)(mt0 + st) * 2048;
#pragma unroll
        for (int j = 0; j < 4; j++)
            cp_async16(a_base + (uint32_t)st * 8192u + (uint32_t)(ltid + j * 128) * 16u,
                       At + ltid + j * 128);
        CP_COMMIT();
    }
    CP_WAIT2();             // B done
    __syncthreads();

    // hoist B fragments to registers
    uint4 bfr[4][4];
#pragma unroll
    for (int jn = 0; jn < 4; jn++)
#pragma unroll
        for (int kp2 = 0; kp2 < 4; kp2++)
            bfr[jn][kp2] = Bsm[(((wn * 4 + jn) * 4 + kp2) << 5) + lane];

    const int gc0 = nt * 128 + wn * 32;

    for (int mi = 0; mi < MGROUP; mi++) {
        if (mi + 1 < MGROUP) CP_WAIT1(); else CP_WAIT0();
        BAR_SYNC(1 + grp, 128);

        if (mi + 2 < MGROUP) {
            const uint4* At = Atile + (size_t)(mt0 + mi + 2) * 2048;
            uint32_t sbase = a_base + (uint32_t)((mi + 2) % 3) * 8192u;
#pragma unroll
            for (int j = 0; j < 4; j++)
                cp_async16(sbase + (uint32_t)(ltid + j * 128) * 16u,
                           At + ltid + j * 128);
            CP_COMMIT();
        }

        const uint4* Acur = reinterpret_cast<const uint4*>(
            smc + (size_t)grp * 3 * 8192 + (size_t)(mi % 3) * 8192);

        float c[2][4][4];
#pragma unroll
        for (int im = 0; im < 2; im++)
#pragma unroll
            for (int jn = 0; jn < 4; jn++)
#pragma unroll
                for (int q = 0; q < 4; q++) c[im][jn][q] = 0.f;

#pragma unroll
        for (int kk = 0; kk < 8; kk++) {
            uint4 af[2];
            af[0] = Acur[((0 * 8 + kk) << 5) + lane];
            af[1] = Acur[((1 * 8 + kk) << 5) + lane];
            int kp2 = kk >> 1;
            int sub = kk & 1;
#pragma unroll
            for (int im = 0; im < 2; im++)
#pragma unroll
                for (int jn = 0; jn < 4; jn++) {
                    uint32_t b0 = sub ? bfr[jn][kp2].z : bfr[jn][kp2].x;
                    uint32_t b1 = sub ? bfr[jn][kp2].w : bfr[jn][kp2].y;
                    mma_f16(c[im][jn], af[im], b0, b1);
                }
        }

        const int m0 = (mt0 + mi) * 128;
        if (nt == 0) {
#pragma unroll
            for (int im = 0; im < 2; im++) {
                int row = m0 + grp * 32 + im * 16 + qid;
#pragma unroll
                for (int jn = 0; jn < 4; jn++) {
                    int col = gc0 + jn * 8 + 2 * rid;
                    *reinterpret_cast<float2*>(hn + (size_t)row * DIMS + col)
                        = make_float2(c[im][jn][0], c[im][jn][1]);
                    *reinterpret_cast<float2*>(hn + (size_t)(row + 8) * DIMS + col)
                        = make_float2(c[im][jn][2], c[im][jn][3]);
                }
            }
        } else {
            int cb = gc0 - DIMS;
#pragma unroll
            for (int im = 0; im < 2; im++) {
                int row = m0 + grp * 32 + im * 16 + qid;
#pragma unroll
                for (int jn = 0; jn < 4; jn++) {
                    int col = cb + jn * 8 + 2 * rid;
                    *reinterpret_cast<__half2*>(T + (size_t)row * TCOL + col)
                        = __floats2half2_rn(c[im][jn][0], c[im][jn][1]);
                    *reinterpret_cast<__half2*>(T + (size_t)(row + 8) * TCOL + col)
                        = __floats2half2_rn(c[im][jn][2], c[im][jn][3]);
                }
            }
        }
    }
}

// -------------------- scoring (relu fused) -----------------------------------
__global__ void score_kernel(const float* __restrict__ h,
                             const int* __restrict__ heads,
                             const int* __restrict__ rels,
                             const int* __restrict__ tails,
                             const float* __restrict__ rel_emb,
                             const float* __restrict__ path_feat,
                             const int* __restrict__ task_idx,
                             const float* __restrict__ delta_w,
                             const float* __restrict__ lambda_logit,
                             const float* __restrict__ rule_init,
                             float* __restrict__ out) {
    int warp = (blockIdx.x * blockDim.x + threadIdx.x) >> 5;
    int lane = threadIdx.x & 31;
    if (warp >= NQUERY) return;
    int hh = heads[warp], rr = rels[warp], tt = tails[warp];
    float4 a = reinterpret_cast<const float4*>(h + (size_t)hh * DIMS)[lane];
    float4 r = reinterpret_cast<const float4*>(rel_emb + (size_t)rr * DIMS)[lane];
    float4 b = reinterpret_cast<const float4*>(h + (size_t)tt * DIMS)[lane];
    a.x = fmaxf(a.x, 0.f); a.y = fmaxf(a.y, 0.f); a.z = fmaxf(a.z, 0.f); a.w = fmaxf(a.w, 0.f);
    b.x = fmaxf(b.x, 0.f); b.y = fmaxf(b.y, 0.f); b.z = fmaxf(b.z, 0.f); b.w = fmaxf(b.w, 0.f);
    float s = a.x * r.x * b.x + a.y * r.y * b.y + a.z * r.z * b.z + a.w * r.w * b.w;
#pragma unroll
    for (int off = 16; off > 0; off >>= 1)
        s += __shfl_xor_sync(0xFFFFFFFFu, s, off);
    if (lane == 0) {
        int idx = task_idx[0];
        float sp = 0.f;
#pragma unroll
        for (int p = 0; p < PDIM; p++)
            sp += path_feat[warp * PDIM + p] * (rule_init[idx * PDIM + p] + delta_w[idx * PDIM + p]);
        float lam = 1.0f / (1.0f + __expf(-lambda_logit[idx]));
        out[warp] = lam * s + (1.0f - lam) * sp;
    }
}

// -------------------- launcher -----------------------------------------------
extern "C" void kernel_launch(void* const* d_in, const int* in_sizes, int n_in,
                              void* d_out, int out_size) {
    const int*   node_ids   = (const int*)d_in[0];
    const int*   edge_index = (const int*)d_in[1];
    const int*   edge_type  = (const int*)d_in[2];
    const int*   heads      = (const int*)d_in[3];
    const int*   rels       = (const int*)d_in[4];
    const int*   tails      = (const int*)d_in[5];
    const float* path_feat  = (const float*)d_in[6];
    const int*   task_idx   = (const int*)d_in[7];
    const float* entity_emb = (const float*)d_in[8];
    const float* rel_emb    = (const float*)d_in[9];
    const float* W_self     = (const float*)d_in[10];
    const float* W_rel      = (const float*)d_in[11];
    const float* delta_w    = (const float*)d_in[12];
    const float* lambda_lg  = (const float*)d_in[13];
    const float* rule_init  = (const float*)d_in[14];
    float*       out        = (float*)d_out;

    const int* src = edge_index;
    const int* dst = edge_index + NEDGE;

    float *hA, *hB;
    __half *T, *Bpack, *Ah;
    uint4* Afrag;
    cudaGetSymbolAddress((void**)&hA, g_hA);
    cudaGetSymbolAddress((void**)&hB, g_hB);
    cudaGetSymbolAddress((void**)&Ah, g_Ah);
    cudaGetSymbolAddress((void**)&T, g_T);
    cudaGetSymbolAddress((void**)&Bpack, g_Bpack);
    cudaGetSymbolAddress((void**)&Afrag, g_Afrag);

    const int TPB = 256;
    cudaFuncSetAttribute(gemm_kernel,
                         cudaFuncAttributeMaxDynamicSharedMemorySize, GEMM_SMEM);
    cudaFuncSetAttribute(convA_kernel,
                         cudaFuncAttributeMaxDynamicSharedMemorySize, 32768);

    // prep (fused pack+zero, then topology sort)
    prep_kernel<<<(NNODES * NRELS + TPB - 1) / TPB, TPB>>>(W_self, W_rel);
    hist_kernel<<<(NEDGE + TPB - 1) / TPB, TPB>>>(dst, edge_type);
    scanA_kernel<<<SCANB, 1024>>>();
    scanB_kernel<<<1, 32>>>();
    scanC_kernel<<<SCANB, 1024>>>();
    scatter_kernel<<<(NEDGE + TPB - 1) / TPB, TPB>>>(src, dst, edge_type);

    dim3 ggrid(NTILES, NTILES);
    const int agg_blocks = (NNODES * 32 + TPB - 1) / TPB;

    // layer 1: A gathered from entity_emb; agg writes relu'd fp16 rows to Ah
    convA_kernel<<<MTILES, 512, 32768>>>(nullptr, node_ids, entity_emb, 0);
    gemm_kernel<<<ggrid, 512, GEMM_SMEM>>>(Afrag, Bpack, T, hB);
    group_agg_kernel<<<agg_blocks, TPB>>>(hB, Ah);
    // layer 2: A from fp16 Ah; agg writes fp32 hA (scoring applies relu)
    convA_kernel<<<MTILES, 512, 32768>>>(Ah, nullptr, nullptr, 1);
    gemm_kernel<<<ggrid, 512, GEMM_SMEM>>>(Afrag, Bpack + (size_t)NCOL * DIMS, T, hA);
    group_agg_kernel<<<agg_blocks, TPB>>>(hA, nullptr);

    score_kernel<<<(NQUERY * 32 + TPB - 1) / TPB, TPB>>>(
        hA, heads, rels, tails, rel_emb, path_feat, task_idx,
        delta_w, lambda_lg, rule_init, out);
}